// round 4
// baseline (speedup 1.0000x reference)
#include <cuda_runtime.h>
#include <math.h>
#include <stdint.h>

#define VOCAB  50257
#define VPAD   50304   // 393*128, padded row length for t1T
#define HDIM   256
#define FDIM   512
#define NBATCH 16
#define SEQT   4096
#define TCAND  4093
#define MSEL   512

// ---------------- device scratch ----------------
__device__ float g_t1T[(size_t)FDIM * VPAD];      // relu(embed@W1+b1), TRANSPOSED [col][row]
__device__ float g_hidden[(size_t)VOCAB * HDIM];
__device__ float g_score[VOCAB];
__device__ int   g_mem_tok[NBATCH * MSEL];
__device__ float g_ctx[NBATCH * HDIM];

__device__ __forceinline__ float wred_sum(float v) {
#pragma unroll
  for (int o = 16; o > 0; o >>= 1) v += __shfl_xor_sync(0xffffffffu, v, o);
  return v;
}
__device__ __forceinline__ uint32_t f2tf32(float f) {
  uint32_t r;
  asm("cvt.rna.tf32.f32 %0, %1;" : "=r"(r) : "f"(f));
  return r;
}
__device__ __forceinline__ float2 split_tf32(float v) {
  uint32_t hi = f2tf32(v);
  float lo = v - __uint_as_float(hi);
  float2 r;
  r.x = __uint_as_float(hi);
  r.y = __uint_as_float(f2tf32(lo));
  return r;
}
// D += A(tf32) * B(tf32), m16n8k8
__device__ __forceinline__ void mma8(float* d, uint32_t a0, uint32_t a1, uint32_t a2,
                                     uint32_t a3, uint32_t b0, uint32_t b1) {
  asm volatile(
      "mma.sync.aligned.m16n8k8.row.col.f32.tf32.tf32.f32 "
      "{%0,%1,%2,%3}, {%4,%5,%6,%7}, {%8,%9}, {%0,%1,%2,%3};"
      : "+f"(d[0]), "+f"(d[1]), "+f"(d[2]), "+f"(d[3])
      : "r"(a0), "r"(a1), "r"(a2), "r"(a3), "r"(b0), "r"(b1));
}

// smem tile row stride: 32 k-elements as 8 quads of [hi(c),lo(c),hi(c+4),lo(c+4)],
// padded 256B payload -> 320B (80 floats) for conflict-free LDS.128
#define RSTR 80

// ============================================================================
// FFN1: t1 = relu(E @ W1 + b1), (V,256)x(256,512). Block 128x128, 256 thr.
// Warp tile 64x32 (2x4 warp grid). Output transposed into g_t1T.
// ============================================================================
#define F1_B_OFF 40960
#define F1_SMEM  81920

__global__ __launch_bounds__(256) void k_ffn1(const float* __restrict__ E,
                                              const float* __restrict__ W1,
                                              const float* __restrict__ b1) {
  extern __shared__ __align__(16) char smem[];
  float* As = (float*)smem;
  float* Bs = (float*)(smem + F1_B_OFF);
  const int tid = threadIdx.x;
  const int lane = tid & 31, wid = tid >> 5;
  const int wm = wid & 1, wn = wid >> 1;
  const int row0 = blockIdx.x * 128;
  const int col0 = blockIdx.y * 128;

  float acc[4][4][4];
#pragma unroll
  for (int mt = 0; mt < 4; mt++)
#pragma unroll
    for (int nt = 0; nt < 4; nt++)
#pragma unroll
      for (int r = 0; r < 4; r++) acc[mt][nt][r] = 0.f;

  for (int ch = 0; ch < 8; ch++) {
    const int k0 = ch * 32;
    if (ch) __syncthreads();
    // stage A: 128 rows x 32 k (1024 float4, 4/thread)
#pragma unroll
    for (int l = 0; l < 4; l++) {
      int idx = tid + l * 256;
      int r = idx >> 3, kq = (idx & 7) << 2;
      int grow = row0 + r;
      float4 v = make_float4(0.f, 0.f, 0.f, 0.f);
      if (grow < VOCAB) v = *(const float4*)(E + (size_t)grow * HDIM + k0 + kq);
      const float vv[4] = {v.x, v.y, v.z, v.w};
#pragma unroll
      for (int e = 0; e < 4; e++) {
        int k = kq + e;
        int s = k >> 3, c = k & 3, h = (k >> 2) & 1;
        *(float2*)(As + r * RSTR + (s * 4 + c) * 4 + h * 2) = split_tf32(vv[e]);
      }
    }
    // stage B: 32 k x 128 n from W1 (1024 float4, 4/thread)
#pragma unroll
    for (int l = 0; l < 4; l++) {
      int idx = tid + l * 256;
      int kk = idx >> 5, n4 = (idx & 31) << 2;
      float4 v = *(const float4*)(W1 + (size_t)(k0 + kk) * FDIM + col0 + n4);
      int s = kk >> 3, c = kk & 3, h = (kk >> 2) & 1;
      int qo = (s * 4 + c) * 4 + h * 2;
      const float vv[4] = {v.x, v.y, v.z, v.w};
#pragma unroll
      for (int e = 0; e < 4; e++) *(float2*)(Bs + (n4 + e) * RSTR + qo) = split_tf32(vv[e]);
    }
    __syncthreads();

#pragma unroll
    for (int s = 0; s < 4; s++) {
      const int qoff = (s * 4 + (lane & 3)) * 4;
      uint4 bw[4];
#pragma unroll
      for (int nt = 0; nt < 4; nt++) {
        int nrow = wn * 32 + nt * 8 + (lane >> 2);
        bw[nt] = *(const uint4*)(Bs + nrow * RSTR + qoff);
      }
#pragma unroll
      for (int mt = 0; mt < 4; mt++) {
        int r1 = wm * 64 + mt * 16 + (lane >> 2);
        uint4 v1 = *(const uint4*)(As + r1 * RSTR + qoff);
        uint4 v2 = *(const uint4*)(As + (r1 + 8) * RSTR + qoff);
#pragma unroll
        for (int nt = 0; nt < 4; nt++) {
          mma8(acc[mt][nt], v1.x, v2.x, v1.z, v2.z, bw[nt].x, bw[nt].z);  // hi*hi
          mma8(acc[mt][nt], v1.x, v2.x, v1.z, v2.z, bw[nt].y, bw[nt].w);  // hi*lo
          mma8(acc[mt][nt], v1.y, v2.y, v1.w, v2.w, bw[nt].x, bw[nt].z);  // lo*hi
        }
      }
    }
  }

  // epilogue: bias + relu, store transposed
#pragma unroll
  for (int nt = 0; nt < 4; nt++) {
#pragma unroll
    for (int j = 0; j < 2; j++) {
      int col = col0 + wn * 32 + nt * 8 + (lane & 3) * 2 + j;
      float bias = b1[col];
      float* dst = g_t1T + (size_t)col * VPAD;
#pragma unroll
      for (int mt = 0; mt < 4; mt++) {
#pragma unroll
        for (int i = 0; i < 2; i++) {
          int row = row0 + wm * 64 + mt * 16 + (lane >> 2) + i * 8;
          if (row < VOCAB) dst[row] = fmaxf(acc[mt][nt][i * 2 + j] + bias, 0.f);
        }
      }
    }
  }
}

// ============================================================================
// FFN2: ff = t1 @ W2 + b2; x = E + ff; LN; hidden + gate score.
// Block 128x256 (full row), 512 thr, warp tile 32x64 (4x4 warp grid).
// ============================================================================
#define F2_PB2  0
#define F2_PLG  256
#define F2_PLB  512
#define F2_PGG  768
#define F2_PLBG 1024
#define F2_PS   1280         // 2 scalars
#define F2_A    1344         // float index (1344*4 = 5376 bytes, 16B aligned)
#define F2_B    (F2_A + 128 * RSTR)
#define F2_SMEM ((F2_B + 256 * RSTR) * 4)

__global__ __launch_bounds__(512) void k_ffn2(const float* __restrict__ E,
                                              const float* __restrict__ W2,
                                              const float* __restrict__ b2,
                                              const float* __restrict__ ln_g,
                                              const float* __restrict__ ln_b,
                                              const float* __restrict__ gate_w,
                                              const float* __restrict__ gate_b) {
  extern __shared__ __align__(16) char smraw[];
  float* sm = (float*)smraw;
  float* As = sm + F2_A;
  float* Bs = sm + F2_B;
  const int tid = threadIdx.x;
  const int lane = tid & 31, wid = tid >> 5;
  const int wm = wid & 3, wn = wid >> 2;
  const int row0 = blockIdx.x * 128;

  if (tid < 256) {
    float gw = gate_w[tid];
    float lg = ln_g[tid], lb = ln_b[tid];
    sm[F2_PB2 + tid] = b2[tid];
    sm[F2_PLG + tid] = lg;
    sm[F2_PLB + tid] = lb;
    sm[F2_PGG + tid] = lg * gw;
    sm[F2_PLBG + tid] = lb * gw;
  }
  __syncthreads();
  if (wid == 0) {
    float s1 = 0.f, s2 = 0.f;
#pragma unroll
    for (int i = 0; i < 8; i++) {
      s1 += sm[F2_PGG + lane + 32 * i];
      s2 += sm[F2_PLBG + lane + 32 * i];
    }
    s1 = wred_sum(s1);
    s2 = wred_sum(s2);
    if (lane == 0) { sm[F2_PS] = s1; sm[F2_PS + 1] = s2; }
  }

  float acc[2][8][4];
#pragma unroll
  for (int mt = 0; mt < 2; mt++)
#pragma unroll
    for (int nt = 0; nt < 8; nt++)
#pragma unroll
      for (int r = 0; r < 4; r++) acc[mt][nt][r] = 0.f;

  for (int ch = 0; ch < 16; ch++) {
    const int k0 = ch * 32;
    __syncthreads();
    // stage A: 128 m x 32 k from g_t1T[k][m] (1024 float4, 2/thread)
#pragma unroll
    for (int l = 0; l < 2; l++) {
      int idx = tid + l * 512;
      int kk = idx >> 5, m4 = (idx & 31) << 2;
      float4 v = *(const float4*)(g_t1T + (size_t)(k0 + kk) * VPAD + row0 + m4);
      int s = kk >> 3, c = kk & 3, h = (kk >> 2) & 1;
      int qo = (s * 4 + c) * 4 + h * 2;
      const float vv[4] = {v.x, v.y, v.z, v.w};
#pragma unroll
      for (int e = 0; e < 4; e++) *(float2*)(As + (m4 + e) * RSTR + qo) = split_tf32(vv[e]);
    }
    // stage B: 32 k x 256 n from W2 (2048 float4, 4/thread)
#pragma unroll
    for (int l = 0; l < 4; l++) {
      int idx = tid + l * 512;
      int kk = idx >> 6, n4 = (idx & 63) << 2;
      float4 v = *(const float4*)(W2 + (size_t)(k0 + kk) * HDIM + n4);
      int s = kk >> 3, c = kk & 3, h = (kk >> 2) & 1;
      int qo = (s * 4 + c) * 4 + h * 2;
      const float vv[4] = {v.x, v.y, v.z, v.w};
#pragma unroll
      for (int e = 0; e < 4; e++) *(float2*)(Bs + (n4 + e) * RSTR + qo) = split_tf32(vv[e]);
    }
    __syncthreads();

#pragma unroll
    for (int s = 0; s < 4; s++) {
      const int qoff = (s * 4 + (lane & 3)) * 4;
      uint4 bw[8];
#pragma unroll
      for (int nt = 0; nt < 8; nt++) {
        int nrow = wn * 64 + nt * 8 + (lane >> 2);
        bw[nt] = *(const uint4*)(Bs + nrow * RSTR + qoff);
      }
#pragma unroll
      for (int mt = 0; mt < 2; mt++) {
        int r1 = wm * 32 + mt * 16 + (lane >> 2);
        uint4 v1 = *(const uint4*)(As + r1 * RSTR + qoff);
        uint4 v2 = *(const uint4*)(As + (r1 + 8) * RSTR + qoff);
#pragma unroll
        for (int nt = 0; nt < 8; nt++) {
          mma8(acc[mt][nt], v1.x, v2.x, v1.z, v2.z, bw[nt].x, bw[nt].z);
          mma8(acc[mt][nt], v1.x, v2.x, v1.z, v2.z, bw[nt].y, bw[nt].w);
          mma8(acc[mt][nt], v1.y, v2.y, v1.w, v2.w, bw[nt].x, bw[nt].z);
        }
      }
    }
  }

  // ---- fused epilogue: residual + LN + gate score ----
  const float fS1 = sm[F2_PS], fS2 = sm[F2_PS + 1];
  __syncthreads();  // done with A/B smem -> overlay partials on A region
  float* pS = As;          // [4][128]
  float* pS2 = As + 512;   // [4][128]
  float* pPG = As + 1024;  // [4][128]
  float* sMU = As + 1536;  // [128]
  float* sRS = As + 1664;  // [128]

#pragma unroll
  for (int mt = 0; mt < 2; mt++) {
#pragma unroll
    for (int i = 0; i < 2; i++) {
      int rl = wm * 32 + mt * 16 + (lane >> 2) + i * 8;
      int rg = row0 + rl;
      bool valid = rg < VOCAB;
      float s = 0.f, s2 = 0.f, pg = 0.f;
#pragma unroll
      for (int nt = 0; nt < 8; nt++) {
#pragma unroll
        for (int j = 0; j < 2; j++) {
          int c = wn * 64 + nt * 8 + (lane & 3) * 2 + j;
          float ev = valid ? E[(size_t)rg * HDIM + c] : 0.f;
          float x = acc[mt][nt][i * 2 + j] + sm[F2_PB2 + c] + ev;
          acc[mt][nt][i * 2 + j] = x;
          s += x;
          s2 += x * x;
          pg += x * sm[F2_PGG + c];
        }
      }
      s += __shfl_xor_sync(0xffffffffu, s, 1);
      s += __shfl_xor_sync(0xffffffffu, s, 2);
      s2 += __shfl_xor_sync(0xffffffffu, s2, 1);
      s2 += __shfl_xor_sync(0xffffffffu, s2, 2);
      pg += __shfl_xor_sync(0xffffffffu, pg, 1);
      pg += __shfl_xor_sync(0xffffffffu, pg, 2);
      if ((lane & 3) == 0) {
        pS[wn * 128 + rl] = s;
        pS2[wn * 128 + rl] = s2;
        pPG[wn * 128 + rl] = pg;
      }
    }
  }
  __syncthreads();
  if (tid < 128) {
    int r = tid;
    float s = pS[r] + pS[128 + r] + pS[256 + r] + pS[384 + r];
    float s2 = pS2[r] + pS2[128 + r] + pS2[256 + r] + pS2[384 + r];
    float pg = pPG[r] + pPG[128 + r] + pPG[256 + r] + pPG[384 + r];
    float mu = s * (1.f / 256.f);
    float var = s2 * (1.f / 256.f) - mu * mu;
    float rs = rsqrtf(var + 1e-5f);
    sMU[r] = mu;
    sRS[r] = rs;
    int rg = row0 + r;
    if (rg < VOCAB) g_score[rg] = rs * (pg - mu * fS1) + fS2 + gate_b[0];
  }
  __syncthreads();

#pragma unroll
  for (int mt = 0; mt < 2; mt++) {
#pragma unroll
    for (int i = 0; i < 2; i++) {
      int rl = wm * 32 + mt * 16 + (lane >> 2) + i * 8;
      int rg = row0 + rl;
      if (rg >= VOCAB) continue;
      float mu = sMU[rl], rs = sRS[rl];
#pragma unroll
      for (int nt = 0; nt < 8; nt++) {
        int c0 = wn * 64 + nt * 8 + (lane & 3) * 2;
        float2 o;
        o.x = (acc[mt][nt][i * 2] - mu) * rs * sm[F2_PLG + c0] + sm[F2_PLB + c0];
        o.y = (acc[mt][nt][i * 2 + 1] - mu) * rs * sm[F2_PLG + c0 + 1] + sm[F2_PLB + c0 + 1];
        *(float2*)(g_hidden + (size_t)rg * HDIM + c0) = o;
      }
    }
  }
}

// ---------------- Pass 3: per-batch top-512 (bitonic sort 4096) ----------------
__global__ __launch_bounds__(1024) void k_topk(const int* __restrict__ seq) {
  __shared__ float sv[4096];
  __shared__ int si[4096];
  const int b = blockIdx.x;
  const int tid = threadIdx.x;

  for (int i = tid; i < 4096; i += 1024) {
    if (i < TCAND) {
      int tok = seq[b * SEQT + i];
      sv[i] = g_score[tok];
      si[i] = i;
    } else {
      sv[i] = -INFINITY;
      si[i] = i;
    }
  }
  __syncthreads();

  for (int k = 2; k <= 4096; k <<= 1) {
    for (int j = k >> 1; j > 0; j >>= 1) {
      for (int t = tid; t < 2048; t += 1024) {
        int i = ((t & ~(j - 1)) << 1) | (t & (j - 1));
        int p = i | j;
        float v1 = sv[i], v2 = sv[p];
        int i1 = si[i], i2 = si[p];
        bool gt = (v1 > v2) || (v1 == v2 && i1 < i2);
        bool desc = ((i & k) == 0);
        if (desc ? !gt : gt) { sv[i] = v2; sv[p] = v1; si[i] = i2; si[p] = i1; }
      }
      __syncthreads();
    }
  }
  for (int m = tid; m < MSEL; m += 1024) g_mem_tok[b * MSEL + m] = seq[b * SEQT + si[m]];
}

// ---------------- Pass 4: query proj + attention + context ----------------
__global__ __launch_bounds__(1024) void k_attn(const int* __restrict__ seq,
                                               const float* __restrict__ qa_w,
                                               const float* __restrict__ qa_b,
                                               const float* __restrict__ qr_w,
                                               const float* __restrict__ qr_b) {
  __shared__ float hq[HDIM], q1[HDIM], q2[HDIM];
  __shared__ float att[MSEL];
  __shared__ int stok[MSEL];
  __shared__ float part[4][HDIM];
  __shared__ float red[32];
  __shared__ float sred[2];
  const int b = blockIdx.x;
  const int tid = threadIdx.x;
  const int lane = tid & 31, w = tid >> 5;
  const int o = tid & 255, p = tid >> 8;

  if (tid < 256) {
    int tokq = seq[b * SEQT + (SEQT - 2)];
    hq[tid] = g_hidden[(size_t)tokq * HDIM + tid];
  }
  if (tid < MSEL) stok[tid] = g_mem_tok[b * MSEL + tid];
  __syncthreads();

  {
    float s = 0.f;
#pragma unroll 8
    for (int h = p * 64; h < p * 64 + 64; h++) s = fmaf(hq[h], qa_w[h * HDIM + o], s);
    part[p][o] = s;
  }
  __syncthreads();
  if (tid < 256) q1[tid] = qa_b[tid] + part[0][tid] + part[1][tid] + part[2][tid] + part[3][tid];
  __syncthreads();
  {
    float s = 0.f;
#pragma unroll 8
    for (int h = p * 64; h < p * 64 + 64; h++) s = fmaf(q1[h], qr_w[h * HDIM + o], s);
    part[p][o] = s;
  }
  __syncthreads();
  if (tid < 256) q2[tid] = qr_b[tid] + part[0][tid] + part[1][tid] + part[2][tid] + part[3][tid];
  __syncthreads();

#pragma unroll 2
  for (int t = 0; t < 16; t++) {
    int m = w * 16 + t;
    const float* row = g_hidden + (size_t)stok[m] * HDIM;
    float s = 0.f;
#pragma unroll
    for (int c = 0; c < 8; c++) s = fmaf(row[lane + 32 * c], q2[lane + 32 * c], s);
    s = wred_sum(s);
    if (lane == 0) att[m] = s;
  }
  __syncthreads();

  float v = (tid < MSEL) ? att[tid] : -INFINITY;
  float mx = v;
#pragma unroll
  for (int off = 16; off > 0; off >>= 1) mx = fmaxf(mx, __shfl_xor_sync(0xffffffffu, mx, off));
  if (lane == 0) red[w] = mx;
  __syncthreads();
  if (w == 0) {
    float m2 = red[lane];
#pragma unroll
    for (int off = 16; off > 0; off >>= 1) m2 = fmaxf(m2, __shfl_xor_sync(0xffffffffu, m2, off));
    if (lane == 0) sred[0] = m2;
  }
  __syncthreads();
  float gmx = sred[0];
  float e = (tid < MSEL) ? expf(v - gmx) : 0.f;
  if (tid < MSEL) att[tid] = e;
  float ssum = wred_sum(e);
  __syncthreads();
  if (lane == 0) red[w] = ssum;
  __syncthreads();
  if (w == 0) {
    float s2 = red[lane];
    s2 = wred_sum(s2);
    if (lane == 0) sred[1] = s2;
  }
  __syncthreads();
  float inv = 1.f / sred[1];

  {
    float c = 0.f;
#pragma unroll 4
    for (int m = p * 128; m < p * 128 + 128; m++)
      c = fmaf(att[m], g_hidden[(size_t)stok[m] * HDIM + o], c);
    part[p][o] = c;
  }
  __syncthreads();
  if (tid < 256)
    g_ctx[b * HDIM + tid] = (part[0][tid] + part[1][tid] + part[2][tid] + part[3][tid]) * inv;
}

// ---------------- Pass 5: out = ctx @ out_w + out_b ----------------
__global__ __launch_bounds__(256) void k_out(const float* __restrict__ Wo,
                                             const float* __restrict__ bo,
                                             float* __restrict__ out) {
  __shared__ float cs[NBATCH * HDIM];
  const int tid = threadIdx.x;
  for (int i = tid; i < NBATCH * HDIM; i += 256) cs[i] = g_ctx[i];
  __syncthreads();
  int v = blockIdx.x * 256 + tid;
  if (v >= VOCAB) return;
  float accv[NBATCH];
  float bias = bo[v];
#pragma unroll
  for (int b = 0; b < NBATCH; b++) accv[b] = bias;
#pragma unroll 8
  for (int h = 0; h < HDIM; h++) {
    float wv = Wo[(size_t)h * VOCAB + v];
#pragma unroll
    for (int b = 0; b < NBATCH; b++) accv[b] = fmaf(cs[b * HDIM + h], wv, accv[b]);
  }
#pragma unroll
  for (int b = 0; b < NBATCH; b++) out[(size_t)b * VOCAB + v] = accv[b];
}

// ---------------- launch ----------------
extern "C" void kernel_launch(void* const* d_in, const int* in_sizes, int n_in,
                              void* d_out, int out_size) {
  const int* seq = (const int*)d_in[0];
  const float* embed = (const float*)d_in[1];
  const float* W1 = (const float*)d_in[2];
  const float* b1 = (const float*)d_in[3];
  const float* W2 = (const float*)d_in[4];
  const float* b2 = (const float*)d_in[5];
  const float* ln_g = (const float*)d_in[6];
  const float* ln_b = (const float*)d_in[7];
  const float* gate_w = (const float*)d_in[8];
  const float* gate_b = (const float*)d_in[9];
  const float* qa_w = (const float*)d_in[10];
  const float* qa_b = (const float*)d_in[11];
  const float* qr_w = (const float*)d_in[12];
  const float* qr_b = (const float*)d_in[13];
  const float* out_w = (const float*)d_in[14];
  const float* out_b = (const float*)d_in[15];
  float* out = (float*)d_out;

  cudaFuncSetAttribute(k_ffn1, cudaFuncAttributeMaxDynamicSharedMemorySize, F1_SMEM);
  cudaFuncSetAttribute(k_ffn2, cudaFuncAttributeMaxDynamicSharedMemorySize, F2_SMEM);

  dim3 g1((VOCAB + 127) / 128, 4);
  k_ffn1<<<g1, 256, F1_SMEM>>>(embed, W1, b1);
  k_ffn2<<<(VOCAB + 127) / 128, 512, F2_SMEM>>>(embed, W2, b2, ln_g, ln_b, gate_w, gate_b);
  k_topk<<<NBATCH, 1024>>>(seq);
  k_attn<<<NBATCH, 1024>>>(seq, qa_w, qa_b, qr_w, qr_b);
  k_out<<<(VOCAB + 255) / 256, 256>>>(out_w, out_b, out);
}

// round 5
// speedup vs baseline: 2.3793x; 2.3793x over previous
#include <cuda_runtime.h>
#include <cuda_fp16.h>
#include <math.h>
#include <stdint.h>

#define VOCAB  50257
#define VPAD   50304
#define HDIM   256
#define FDIM   512
#define NBATCH 16
#define SEQT   4096
#define TCAND  4093
#define MSEL   512
#define INV2048 (1.0f / 2048.0f)

// ---------------- device scratch ----------------
// pair format: uint2 = { half2(hi(k), hi(k+1)), half2(lo(k)*2048, lo(k+1)*2048) }
__device__ uint2 g_t1p[(size_t)VPAD * 256];   // t1 pre-split, [m][kpair], 103MB
__device__ uint2 g_w1p[FDIM * 128];           // W1 pre-split, [n][kpair]
__device__ uint2 g_w2p[HDIM * 256];           // W2 pre-split, [n][kpair]
__device__ float g_hidden[(size_t)VOCAB * HDIM];
__device__ float g_score[VOCAB];
__device__ int   g_mem_tok[NBATCH * MSEL];
__device__ float g_ctx[NBATCH * HDIM];

// ---------------- helpers ----------------
__device__ __forceinline__ float wred_sum(float v) {
#pragma unroll
  for (int o = 16; o > 0; o >>= 1) v += __shfl_xor_sync(0xffffffffu, v, o);
  return v;
}
__device__ __forceinline__ uint2 splitpair(float x0, float x1) {
  __half h0 = __float2half_rn(x0);
  __half h1 = __float2half_rn(x1);
  float r0 = (x0 - __half2float(h0)) * 2048.f;
  float r1 = (x1 - __half2float(h1)) * 2048.f;
  __half2 hp = __halves2half2(h0, h1);
  __half2 lp = __floats2half2_rn(r0, r1);
  uint2 u;
  u.x = *(uint32_t*)&hp;
  u.y = *(uint32_t*)&lp;
  return u;
}
__device__ __forceinline__ void mma16(float* d, uint32_t a0, uint32_t a1, uint32_t a2,
                                      uint32_t a3, uint32_t b0, uint32_t b1) {
  asm volatile(
      "mma.sync.aligned.m16n8k16.row.col.f32.f16.f16.f32 "
      "{%0,%1,%2,%3}, {%4,%5,%6,%7}, {%8,%9}, {%0,%1,%2,%3};"
      : "+f"(d[0]), "+f"(d[1]), "+f"(d[2]), "+f"(d[3])
      : "r"(a0), "r"(a1), "r"(a2), "r"(a3), "r"(b0), "r"(b1));
}
__device__ __forceinline__ void cpa16(void* smem_dst, const void* gsrc) {
  uint32_t s = (uint32_t)__cvta_generic_to_shared(smem_dst);
  asm volatile("cp.async.cg.shared.global [%0], [%1], 16;" :: "r"(s), "l"(gsrc));
}
#define CP_COMMIT asm volatile("cp.async.commit_group;")
#define CP_WAIT0  asm volatile("cp.async.wait_group 0;" ::: "memory")

#define RB 160  // smem row stride bytes (payload 128 = 16 pairs x 8B), conflict-free

// ---------------- prep: pre-split W1, W2 into pair format ----------------
__global__ __launch_bounds__(256) void k_prep(const float* __restrict__ W1,
                                              const float* __restrict__ W2) {
  int g = blockIdx.x * 256 + threadIdx.x;
  if (g < FDIM * 128) {
    int n = g >> 7, c = g & 127;
    g_w1p[n * 128 + c] = splitpair(W1[(2 * c) * FDIM + n], W1[(2 * c + 1) * FDIM + n]);
  } else {
    g -= FDIM * 128;
    if (g < HDIM * 256) {
      int n = g >> 8, c = g & 255;
      g_w2p[n * 256 + c] = splitpair(W2[(2 * c) * HDIM + n], W2[(2 * c + 1) * HDIM + n]);
    }
  }
}

// ============================================================================
// FFN1: t1 = relu(E @ W1 + b1). Block 128x128, 512 thr (4x4 warps, 32x32 tiles).
// K = 256 in 8 chunks of 32. Output pre-split into g_t1p.
// ============================================================================
#define F1_A0 0
#define F1_A1 20480
#define F1_B0 40960
#define F1_B1 61440
#define F1_SMEM 81920

__global__ __launch_bounds__(512) void k_ffn1(const float* __restrict__ E,
                                              const float* __restrict__ b1) {
  extern __shared__ __align__(16) char sm[];
  const int tid = threadIdx.x, lane = tid & 31, wid = tid >> 5;
  const int gr = lane >> 2, tc = lane & 3;
  const int wm = wid & 3, wn = wid >> 2;
  const int row0 = blockIdx.x * 128, col0 = blockIdx.y * 128;

  float acc0[2][4][4], acc1[2][4][4];
#pragma unroll
  for (int mt = 0; mt < 2; mt++)
#pragma unroll
    for (int nt = 0; nt < 4; nt++)
#pragma unroll
      for (int r = 0; r < 4; r++) { acc0[mt][nt][r] = 0.f; acc1[mt][nt][r] = 0.f; }

  // prologue: stage chunk 0
  {
    char* Ab = sm + F1_A0;
#pragma unroll
    for (int l = 0; l < 2; l++) {
      int idx = tid + l * 512;
      int r = idx >> 3, q = idx & 7;
      int grow = row0 + r;
      float4 v = make_float4(0.f, 0.f, 0.f, 0.f);
      if (grow < VOCAB) v = *(const float4*)(E + (size_t)grow * HDIM + q * 4);
      uint2 u01 = splitpair(v.x, v.y), u23 = splitpair(v.z, v.w);
      *(uint4*)(Ab + r * RB + q * 16) = make_uint4(u01.x, u01.y, u23.x, u23.y);
    }
    char* Bb = sm + F1_B0;
#pragma unroll
    for (int l = 0; l < 2; l++) {
      int idx = tid + l * 512;
      int nr = idx >> 3, u = idx & 7;
      cpa16(Bb + nr * RB + u * 16, g_w1p + (size_t)(col0 + nr) * 128 + u * 2);
    }
    CP_COMMIT;
  }

#pragma unroll 1
  for (int ch = 0; ch < 8; ch++) {
    char* Ab = sm + ((ch & 1) ? F1_A1 : F1_A0);
    char* Bb = sm + ((ch & 1) ? F1_B1 : F1_B0);
    char* An = sm + ((ch & 1) ? F1_A0 : F1_A1);
    char* Bn = sm + ((ch & 1) ? F1_B0 : F1_B1);
    CP_WAIT0;
    __syncthreads();
    const bool more = (ch + 1) < 8;
    float4 pre[2];
    if (more) {
#pragma unroll
      for (int l = 0; l < 2; l++) {
        int idx = tid + l * 512;
        int nr = idx >> 3, u = idx & 7;
        cpa16(Bn + nr * RB + u * 16,
              g_w1p + (size_t)(col0 + nr) * 128 + (ch + 1) * 16 + u * 2);
      }
      CP_COMMIT;
#pragma unroll
      for (int l = 0; l < 2; l++) {
        int idx = tid + l * 512;
        int r = idx >> 3, q = idx & 7;
        int grow = row0 + r;
        pre[l] = make_float4(0.f, 0.f, 0.f, 0.f);
        if (grow < VOCAB)
          pre[l] = *(const float4*)(E + (size_t)grow * HDIM + (ch + 1) * 32 + q * 4);
      }
    }
    // MMA on current chunk
#pragma unroll
    for (int h = 0; h < 2; h++) {
      uint2 bf0[4], bf1[4];
#pragma unroll
      for (int nt = 0; nt < 4; nt++) {
        char* bp = Bb + (wn * 32 + nt * 8 + gr) * RB + (h * 8 + tc) * 8;
        bf0[nt] = *(uint2*)bp;
        bf1[nt] = *(uint2*)(bp + 32);
      }
#pragma unroll
      for (int mt = 0; mt < 2; mt++) {
        char* ap = Ab + (wm * 32 + mt * 16 + gr) * RB + (h * 8 + tc) * 8;
        uint2 a0 = *(uint2*)ap;
        uint2 a1 = *(uint2*)(ap + 8 * RB);
        uint2 a2 = *(uint2*)(ap + 32);
        uint2 a3 = *(uint2*)(ap + 8 * RB + 32);
#pragma unroll
        for (int nt = 0; nt < 4; nt++) {
          mma16(acc0[mt][nt], a0.x, a1.x, a2.x, a3.x, bf0[nt].x, bf1[nt].x);
          mma16(acc1[mt][nt], a0.x, a1.x, a2.x, a3.x, bf0[nt].y, bf1[nt].y);
          mma16(acc1[mt][nt], a0.y, a1.y, a2.y, a3.y, bf0[nt].x, bf1[nt].x);
        }
      }
    }
    if (more) {
#pragma unroll
      for (int l = 0; l < 2; l++) {
        int idx = tid + l * 512;
        int r = idx >> 3, q = idx & 7;
        uint2 u01 = splitpair(pre[l].x, pre[l].y), u23 = splitpair(pre[l].z, pre[l].w);
        *(uint4*)(An + r * RB + q * 16) = make_uint4(u01.x, u01.y, u23.x, u23.y);
      }
    }
    __syncthreads();
  }

  // epilogue: combine, bias+relu, pre-split store
#pragma unroll
  for (int mt = 0; mt < 2; mt++) {
#pragma unroll
    for (int nt = 0; nt < 4; nt++) {
      int c0 = col0 + wn * 32 + nt * 8 + tc * 2;
      float bb0 = b1[c0], bb1 = b1[c0 + 1];
#pragma unroll
      for (int i = 0; i < 2; i++) {
        int row = row0 + wm * 32 + mt * 16 + gr + i * 8;
        if (row < VOCAB) {
          float v0 = fmaxf(acc0[mt][nt][i * 2] + acc1[mt][nt][i * 2] * INV2048 + bb0, 0.f);
          float v1 = fmaxf(acc0[mt][nt][i * 2 + 1] + acc1[mt][nt][i * 2 + 1] * INV2048 + bb1, 0.f);
          g_t1p[(size_t)row * 256 + (c0 >> 1)] = splitpair(v0, v1);
        }
      }
    }
  }
}

// ============================================================================
// FFN2: ff = t1 @ W2 + b2; x = E + ff; LN; hidden + gate score.
// Block 64x256 (full row), 512 thr (2x8 warps, 32x32 tiles). K = 512, 16 chunks.
// All staging is cp.async (operands pre-split).
// ============================================================================
#define F2_A0 0
#define F2_A1 10240
#define F2_B0 20480
#define F2_B1 61440
#define F2_PAR 102400               // sb2, slg, slb, sgg: 4 x 256 floats
#define F2_PS  (F2_PAR + 4096)      // [8][64]
#define F2_PS2 (F2_PS + 2048)
#define F2_PPG (F2_PS2 + 2048)
#define F2_MU  (F2_PPG + 2048)      // [64]
#define F2_RS  (F2_MU + 256)        // [64]
#define F2_SS  (F2_RS + 256)        // s1, s2+gb
#define F2_SMEM (F2_SS + 16)

__global__ __launch_bounds__(512) void k_ffn2(const float* __restrict__ E,
                                              const float* __restrict__ b2,
                                              const float* __restrict__ ln_g,
                                              const float* __restrict__ ln_b,
                                              const float* __restrict__ gate_w,
                                              const float* __restrict__ gate_b) {
  extern __shared__ __align__(16) char sm[];
  float* sb2 = (float*)(sm + F2_PAR);
  float* slg = sb2 + 256;
  float* slb = slg + 256;
  float* sgg = slb + 256;
  float* pS = (float*)(sm + F2_PS);
  float* pS2 = (float*)(sm + F2_PS2);
  float* pPG = (float*)(sm + F2_PPG);
  float* sMU = (float*)(sm + F2_MU);
  float* sRS = (float*)(sm + F2_RS);
  float* sS = (float*)(sm + F2_SS);
  const int tid = threadIdx.x, lane = tid & 31, wid = tid >> 5;
  const int gr = lane >> 2, tc = lane & 3;
  const int wm = wid & 1, wn = wid >> 1;
  const int row0 = blockIdx.x * 64;

  if (tid < 256) {
    float lg = ln_g[tid], lb = ln_b[tid], gw = gate_w[tid];
    sb2[tid] = b2[tid];
    slg[tid] = lg;
    slb[tid] = lb;
    sgg[tid] = lg * gw;
  }

  float acc0[2][4][4], acc1[2][4][4];
#pragma unroll
  for (int mt = 0; mt < 2; mt++)
#pragma unroll
    for (int nt = 0; nt < 4; nt++)
#pragma unroll
      for (int r = 0; r < 4; r++) { acc0[mt][nt][r] = 0.f; acc1[mt][nt][r] = 0.f; }

  // prologue: chunk 0 (A: 512 units of 16B; B: 2048 units)
  {
    int nr = tid >> 3, u = tid & 7;
    cpa16(sm + F2_A0 + nr * RB + u * 16, g_t1p + (size_t)(row0 + nr) * 256 + u * 2);
#pragma unroll
    for (int l = 0; l < 4; l++) {
      int idx = tid + l * 512;
      int br = idx >> 3, bu = idx & 7;
      cpa16(sm + F2_B0 + br * RB + bu * 16, g_w2p + (size_t)br * 256 + bu * 2);
    }
    CP_COMMIT;
  }

#pragma unroll 1
  for (int ch = 0; ch < 16; ch++) {
    char* Ab = sm + ((ch & 1) ? F2_A1 : F2_A0);
    char* Bb = sm + ((ch & 1) ? F2_B1 : F2_B0);
    char* An = sm + ((ch & 1) ? F2_A0 : F2_A1);
    char* Bn = sm + ((ch & 1) ? F2_B0 : F2_B1);
    CP_WAIT0;
    __syncthreads();
    if (ch + 1 < 16) {
      int nr = tid >> 3, u = tid & 7;
      cpa16(An + nr * RB + u * 16,
            g_t1p + (size_t)(row0 + nr) * 256 + (ch + 1) * 16 + u * 2);
#pragma unroll
      for (int l = 0; l < 4; l++) {
        int idx = tid + l * 512;
        int br = idx >> 3, bu = idx & 7;
        cpa16(Bn + br * RB + bu * 16, g_w2p + (size_t)br * 256 + (ch + 1) * 16 + bu * 2);
      }
      CP_COMMIT;
    }
#pragma unroll
    for (int h = 0; h < 2; h++) {
      uint2 bf0[4], bf1[4];
#pragma unroll
      for (int nt = 0; nt < 4; nt++) {
        char* bp = Bb + (wn * 32 + nt * 8 + gr) * RB + (h * 8 + tc) * 8;
        bf0[nt] = *(uint2*)bp;
        bf1[nt] = *(uint2*)(bp + 32);
      }
#pragma unroll
      for (int mt = 0; mt < 2; mt++) {
        char* ap = Ab + (wm * 32 + mt * 16 + gr) * RB + (h * 8 + tc) * 8;
        uint2 a0 = *(uint2*)ap;
        uint2 a1 = *(uint2*)(ap + 8 * RB);
        uint2 a2 = *(uint2*)(ap + 32);
        uint2 a3 = *(uint2*)(ap + 8 * RB + 32);
#pragma unroll
        for (int nt = 0; nt < 4; nt++) {
          mma16(acc0[mt][nt], a0.x, a1.x, a2.x, a3.x, bf0[nt].x, bf1[nt].x);
          mma16(acc1[mt][nt], a0.x, a1.x, a2.x, a3.x, bf0[nt].y, bf1[nt].y);
          mma16(acc1[mt][nt], a0.y, a1.y, a2.y, a3.y, bf0[nt].x, bf1[nt].x);
        }
      }
    }
    __syncthreads();
  }

  // s1 = sum(lg*gw), s2 = sum(lb*gw) + gate_b
  if (wid == 0) {
    float a = 0.f, b = 0.f;
#pragma unroll
    for (int i = 0; i < 8; i++) {
      a += sgg[lane + 32 * i];
      b += slb[lane + 32 * i] * gate_w[lane + 32 * i];
    }
    a = wred_sum(a);
    b = wred_sum(b);
    if (lane == 0) { sS[0] = a; sS[1] = b + gate_b[0]; }
  }

  // pass 1: combine + residual, accumulate row stats
#pragma unroll
  for (int mt = 0; mt < 2; mt++) {
#pragma unroll
    for (int i = 0; i < 2; i++) {
      int rl = wm * 32 + mt * 16 + gr + i * 8;
      int rg = row0 + rl;
      bool valid = rg < VOCAB;
      float s = 0.f, sq = 0.f, pg = 0.f;
#pragma unroll
      for (int nt = 0; nt < 4; nt++) {
        int c0 = wn * 32 + nt * 8 + tc * 2;
        float2 ev = make_float2(0.f, 0.f);
        if (valid) ev = *(const float2*)(E + (size_t)rg * HDIM + c0);
        float x0 = acc0[mt][nt][i * 2] + acc1[mt][nt][i * 2] * INV2048 + sb2[c0] + ev.x;
        float x1 = acc0[mt][nt][i * 2 + 1] + acc1[mt][nt][i * 2 + 1] * INV2048 + sb2[c0 + 1] + ev.y;
        acc0[mt][nt][i * 2] = x0;
        acc0[mt][nt][i * 2 + 1] = x1;
        s += x0 + x1;
        sq += x0 * x0 + x1 * x1;
        pg += x0 * sgg[c0] + x1 * sgg[c0 + 1];
      }
      s += __shfl_xor_sync(0xffffffffu, s, 1);
      s += __shfl_xor_sync(0xffffffffu, s, 2);
      sq += __shfl_xor_sync(0xffffffffu, sq, 1);
      sq += __shfl_xor_sync(0xffffffffu, sq, 2);
      pg += __shfl_xor_sync(0xffffffffu, pg, 1);
      pg += __shfl_xor_sync(0xffffffffu, pg, 2);
      if (tc == 0) {
        pS[wn * 64 + rl] = s;
        pS2[wn * 64 + rl] = sq;
        pPG[wn * 64 + rl] = pg;
      }
    }
  }
  __syncthreads();
  if (tid < 64) {
    float s = 0.f, sq = 0.f, pg = 0.f;
#pragma unroll
    for (int w = 0; w < 8; w++) {
      s += pS[w * 64 + tid];
      sq += pS2[w * 64 + tid];
      pg += pPG[w * 64 + tid];
    }
    float mu = s * (1.f / 256.f);
    float var = sq * (1.f / 256.f) - mu * mu;
    float rs = rsqrtf(var + 1e-5f);
    sMU[tid] = mu;
    sRS[tid] = rs;
    int rg = row0 + tid;
    if (rg < VOCAB) g_score[rg] = rs * (pg - mu * sS[0]) + sS[1];
  }
  __syncthreads();

  // pass 2: normalize + store hidden
#pragma unroll
  for (int mt = 0; mt < 2; mt++) {
#pragma unroll
    for (int i = 0; i < 2; i++) {
      int rl = wm * 32 + mt * 16 + gr + i * 8;
      int rg = row0 + rl;
      if (rg >= VOCAB) continue;
      float mu = sMU[rl], rs = sRS[rl];
#pragma unroll
      for (int nt = 0; nt < 4; nt++) {
        int c0 = wn * 32 + nt * 8 + tc * 2;
        float2 o;
        o.x = (acc0[mt][nt][i * 2] - mu) * rs * slg[c0] + slb[c0];
        o.y = (acc0[mt][nt][i * 2 + 1] - mu) * rs * slg[c0 + 1] + slb[c0 + 1];
        *(float2*)(g_hidden + (size_t)rg * HDIM + c0) = o;
      }
    }
  }
}

// ---------------- Pass 3: per-batch top-512 (bitonic sort 4096) ----------------
__global__ __launch_bounds__(1024) void k_topk(const int* __restrict__ seq) {
  __shared__ float sv[4096];
  __shared__ int si[4096];
  const int b = blockIdx.x;
  const int tid = threadIdx.x;

  for (int i = tid; i < 4096; i += 1024) {
    if (i < TCAND) {
      int tok = seq[b * SEQT + i];
      sv[i] = g_score[tok];
      si[i] = i;
    } else {
      sv[i] = -INFINITY;
      si[i] = i;
    }
  }
  __syncthreads();

  for (int k = 2; k <= 4096; k <<= 1) {
    for (int j = k >> 1; j > 0; j >>= 1) {
      for (int t = tid; t < 2048; t += 1024) {
        int i = ((t & ~(j - 1)) << 1) | (t & (j - 1));
        int p = i | j;
        float v1 = sv[i], v2 = sv[p];
        int i1 = si[i], i2 = si[p];
        bool gt = (v1 > v2) || (v1 == v2 && i1 < i2);
        bool desc = ((i & k) == 0);
        if (desc ? !gt : gt) { sv[i] = v2; sv[p] = v1; si[i] = i2; si[p] = i1; }
      }
      __syncthreads();
    }
  }
  for (int m = tid; m < MSEL; m += 1024) g_mem_tok[b * MSEL + m] = seq[b * SEQT + si[m]];
}

// ---------------- Pass 4: query proj + attention + context ----------------
__global__ __launch_bounds__(1024) void k_attn(const int* __restrict__ seq,
                                               const float* __restrict__ qa_w,
                                               const float* __restrict__ qa_b,
                                               const float* __restrict__ qr_w,
                                               const float* __restrict__ qr_b) {
  __shared__ float hq[HDIM], q1[HDIM], q2[HDIM];
  __shared__ float att[MSEL];
  __shared__ int stok[MSEL];
  __shared__ float part[4][HDIM];
  __shared__ float red[32];
  __shared__ float sred[2];
  const int b = blockIdx.x;
  const int tid = threadIdx.x;
  const int lane = tid & 31, w = tid >> 5;
  const int o = tid & 255, p = tid >> 8;

  if (tid < 256) {
    int tokq = seq[b * SEQT + (SEQT - 2)];
    hq[tid] = g_hidden[(size_t)tokq * HDIM + tid];
  }
  if (tid < MSEL) stok[tid] = g_mem_tok[b * MSEL + tid];
  __syncthreads();

  {
    float s = 0.f;
#pragma unroll 8
    for (int h = p * 64; h < p * 64 + 64; h++) s = fmaf(hq[h], qa_w[h * HDIM + o], s);
    part[p][o] = s;
  }
  __syncthreads();
  if (tid < 256) q1[tid] = qa_b[tid] + part[0][tid] + part[1][tid] + part[2][tid] + part[3][tid];
  __syncthreads();
  {
    float s = 0.f;
#pragma unroll 8
    for (int h = p * 64; h < p * 64 + 64; h++) s = fmaf(q1[h], qr_w[h * HDIM + o], s);
    part[p][o] = s;
  }
  __syncthreads();
  if (tid < 256) q2[tid] = qr_b[tid] + part[0][tid] + part[1][tid] + part[2][tid] + part[3][tid];
  __syncthreads();

#pragma unroll 2
  for (int t = 0; t < 16; t++) {
    int m = w * 16 + t;
    const float* row = g_hidden + (size_t)stok[m] * HDIM;
    float s = 0.f;
#pragma unroll
    for (int c = 0; c < 8; c++) s = fmaf(row[lane + 32 * c], q2[lane + 32 * c], s);
    s = wred_sum(s);
    if (lane == 0) att[m] = s;
  }
  __syncthreads();

  float v = (tid < MSEL) ? att[tid] : -INFINITY;
  float mx = v;
#pragma unroll
  for (int off = 16; off > 0; off >>= 1) mx = fmaxf(mx, __shfl_xor_sync(0xffffffffu, mx, off));
  if (lane == 0) red[w] = mx;
  __syncthreads();
  if (w == 0) {
    float m2 = red[lane];
#pragma unroll
    for (int off = 16; off > 0; off >>= 1) m2 = fmaxf(m2, __shfl_xor_sync(0xffffffffu, m2, off));
    if (lane == 0) sred[0] = m2;
  }
  __syncthreads();
  float gmx = sred[0];
  float e = (tid < MSEL) ? expf(v - gmx) : 0.f;
  if (tid < MSEL) att[tid] = e;
  float ssum = wred_sum(e);
  __syncthreads();
  if (lane == 0) red[w] = ssum;
  __syncthreads();
  if (w == 0) {
    float s2 = red[lane];
    s2 = wred_sum(s2);
    if (lane == 0) sred[1] = s2;
  }
  __syncthreads();
  float inv = 1.f / sred[1];

  {
    float c = 0.f;
#pragma unroll 4
    for (int m = p * 128; m < p * 128 + 128; m++)
      c = fmaf(att[m], g_hidden[(size_t)stok[m] * HDIM + o], c);
    part[p][o] = c;
  }
  __syncthreads();
  if (tid < 256)
    g_ctx[b * HDIM + tid] = (part[0][tid] + part[1][tid] + part[2][tid] + part[3][tid]) * inv;
}

// ---------------- Pass 5: out = ctx @ out_w + out_b ----------------
__global__ __launch_bounds__(256) void k_out(const float* __restrict__ Wo,
                                             const float* __restrict__ bo,
                                             float* __restrict__ out) {
  __shared__ float cs[NBATCH * HDIM];
  const int tid = threadIdx.x;
  for (int i = tid; i < NBATCH * HDIM; i += 256) cs[i] = g_ctx[i];
  __syncthreads();
  int v = blockIdx.x * 256 + tid;
  if (v >= VOCAB) return;
  float accv[NBATCH];
  float bias = bo[v];
#pragma unroll
  for (int b = 0; b < NBATCH; b++) accv[b] = bias;
#pragma unroll 8
  for (int h = 0; h < HDIM; h++) {
    float wv = Wo[(size_t)h * VOCAB + v];
#pragma unroll
    for (int b = 0; b < NBATCH; b++) accv[b] = fmaf(cs[b * HDIM + h], wv, accv[b]);
  }
#pragma unroll
  for (int b = 0; b < NBATCH; b++) out[(size_t)b * VOCAB + v] = accv[b];
}

// ---------------- launch ----------------
extern "C" void kernel_launch(void* const* d_in, const int* in_sizes, int n_in,
                              void* d_out, int out_size) {
  const int* seq = (const int*)d_in[0];
  const float* embed = (const float*)d_in[1];
  const float* W1 = (const float*)d_in[2];
  const float* b1 = (const float*)d_in[3];
  const float* W2 = (const float*)d_in[4];
  const float* b2 = (const float*)d_in[5];
  const float* ln_g = (const float*)d_in[6];
  const float* ln_b = (const float*)d_in[7];
  const float* gate_w = (const float*)d_in[8];
  const float* gate_b = (const float*)d_in[9];
  const float* qa_w = (const float*)d_in[10];
  const float* qa_b = (const float*)d_in[11];
  const float* qr_w = (const float*)d_in[12];
  const float* qr_b = (const float*)d_in[13];
  const float* out_w = (const float*)d_in[14];
  const float* out_b = (const float*)d_in[15];
  float* out = (float*)d_out;

  cudaFuncSetAttribute(k_ffn1, cudaFuncAttributeMaxDynamicSharedMemorySize, F1_SMEM);
  cudaFuncSetAttribute(k_ffn2, cudaFuncAttributeMaxDynamicSharedMemorySize, F2_SMEM);

  k_prep<<<512, 256>>>(W1, W2);
  dim3 g1((VOCAB + 127) / 128, 4);
  k_ffn1<<<g1, 512, F1_SMEM>>>(embed, b1);
  k_ffn2<<<(VOCAB + 63) / 64, 512, F2_SMEM>>>(embed, b2, ln_g, ln_b, gate_w, gate_b);
  k_topk<<<NBATCH, 1024>>>(seq);
  k_attn<<<NBATCH, 1024>>>(seq, qa_w, qa_b, qr_w, qr_b);
  k_out<<<(VOCAB + 255) / 256, 256>>>(out_w, out_b, out);
}

// round 7
// speedup vs baseline: 3.0361x; 1.2760x over previous
#include <cuda_runtime.h>
#include <cuda_fp16.h>
#include <math.h>
#include <stdint.h>

#define VOCAB  50257
#define VPAD   50304
#define HDIM   256
#define FDIM   512
#define NBATCH 16
#define SEQT   4096
#define TCAND  4093
#define MSEL   512
#define INV2048 (1.0f / 2048.0f)

// ---------------- device scratch ----------------
// pair format: uint2 = { half2(hi(k), hi(k+1)), half2(lo(k)*2048, lo(k+1)*2048) }
__device__ uint2 g_t1p[(size_t)VPAD * 256];   // t1 pre-split, [compact_row][kpair]
__device__ uint2 g_w1p[FDIM * 128];           // W1 pre-split, [n][kpair]
__device__ uint2 g_w2p[HDIM * 256];           // W2 pre-split, [n][kpair]
__device__ float g_hidden[(size_t)VPAD * HDIM];  // per compact row
__device__ float g_score[VPAD];                  // per compact row
__device__ int   g_mem_tok[NBATCH * MSEL];       // compact ids
__device__ float g_ctx[NBATCH * HDIM];
// compaction
__device__ int g_flag[VOCAB];
__device__ int g_comp[VOCAB];
__device__ int g_list[VPAD];
__device__ int g_count;

// ---------------- helpers ----------------
__device__ __forceinline__ float wred_sum(float v) {
#pragma unroll
  for (int o = 16; o > 0; o >>= 1) v += __shfl_xor_sync(0xffffffffu, v, o);
  return v;
}
__device__ __forceinline__ uint2 splitpair(float x0, float x1) {
  __half h0 = __float2half_rn(x0);
  __half h1 = __float2half_rn(x1);
  float r0 = (x0 - __half2float(h0)) * 2048.f;
  float r1 = (x1 - __half2float(h1)) * 2048.f;
  __half2 hp = __halves2half2(h0, h1);
  __half2 lp = __floats2half2_rn(r0, r1);
  uint2 u;
  u.x = *(uint32_t*)&hp;
  u.y = *(uint32_t*)&lp;
  return u;
}
__device__ __forceinline__ void mma16(float* d, uint32_t a0, uint32_t a1, uint32_t a2,
                                      uint32_t a3, uint32_t b0, uint32_t b1) {
  asm volatile(
      "mma.sync.aligned.m16n8k16.row.col.f32.f16.f16.f32 "
      "{%0,%1,%2,%3}, {%4,%5,%6,%7}, {%8,%9}, {%0,%1,%2,%3};"
      : "+f"(d[0]), "+f"(d[1]), "+f"(d[2]), "+f"(d[3])
      : "r"(a0), "r"(a1), "r"(a2), "r"(a3), "r"(b0), "r"(b1));
}
__device__ __forceinline__ void cpa16(void* smem_dst, const void* gsrc) {
  uint32_t s = (uint32_t)__cvta_generic_to_shared(smem_dst);
  asm volatile("cp.async.cg.shared.global [%0], [%1], 16;" :: "r"(s), "l"(gsrc));
}
#define CP_COMMIT asm volatile("cp.async.commit_group;")
#define CP_WAIT0  asm volatile("cp.async.wait_group 0;" ::: "memory")

#define RB 160  // smem row stride bytes (payload 128 = 16 pairs x 8B), conflict-free

// ---------------- compaction ----------------
__global__ __launch_bounds__(1024) void k_clear() {
  int i = blockIdx.x * 1024 + threadIdx.x;
  if (i < VOCAB) {
    g_flag[i] = 0;
    g_comp[i] = 0;
  }
  if (i == 0) g_count = 0;
}
// mark tokens from seq[:, 0:4093] and seq[:, 4094]; assign compact ids
__global__ __launch_bounds__(1024) void k_mark(const int* __restrict__ seq) {
  int i = blockIdx.x * 1024 + threadIdx.x;
  if (i >= NBATCH * (TCAND + 1)) return;
  int b = i / (TCAND + 1);
  int j = i - b * (TCAND + 1);
  int pos = (j < TCAND) ? j : (SEQT - 2);
  int tok = seq[b * SEQT + pos];
  if (atomicExch(&g_flag[tok], 1) == 0) {
    int id = atomicAdd(&g_count, 1);
    g_comp[tok] = id;
    g_list[id] = tok;
  }
}

// ---------------- prep: pre-split W1, W2 into pair format ----------------
__global__ __launch_bounds__(256) void k_prep(const float* __restrict__ W1,
                                              const float* __restrict__ W2) {
  int g = blockIdx.x * 256 + threadIdx.x;
  if (g < FDIM * 128) {
    int n = g >> 7, c = g & 127;
    g_w1p[n * 128 + c] = splitpair(W1[(2 * c) * FDIM + n], W1[(2 * c + 1) * FDIM + n]);
  } else {
    g -= FDIM * 128;
    if (g < HDIM * 256) {
      int n = g >> 8, c = g & 255;
      g_w2p[n * 256 + c] = splitpair(W2[(2 * c) * HDIM + n], W2[(2 * c + 1) * HDIM + n]);
    }
  }
}

// ============================================================================
// FFN1: t1 = relu(E[list] @ W1 + b1) over compact rows. Block 128x128, 512 thr.
// ============================================================================
#define F1_A0 0
#define F1_A1 20480
#define F1_B0 40960
#define F1_B1 61440
#define F1_SMEM 81920

__global__ __launch_bounds__(512) void k_ffn1(const float* __restrict__ E,
                                              const float* __restrict__ b1) {
  extern __shared__ __align__(16) char sm[];
  __shared__ int slist[128];
  const int tid = threadIdx.x, lane = tid & 31, wid = tid >> 5;
  const int gr = lane >> 2, tc = lane & 3;
  const int wm = wid & 3, wn = wid >> 2;
  const int row0 = blockIdx.x * 128, col0 = blockIdx.y * 128;

  const int cnt = g_count;
  if (row0 >= cnt) return;
  if (tid < 128) slist[tid] = (row0 + tid < cnt) ? g_list[row0 + tid] : -1;
  __syncthreads();

  float acc0[2][4][4], acc1[2][4][4];
#pragma unroll
  for (int mt = 0; mt < 2; mt++)
#pragma unroll
    for (int nt = 0; nt < 4; nt++)
#pragma unroll
      for (int r = 0; r < 4; r++) { acc0[mt][nt][r] = 0.f; acc1[mt][nt][r] = 0.f; }

  // prologue: stage chunk 0
  {
    char* Ab = sm + F1_A0;
#pragma unroll
    for (int l = 0; l < 2; l++) {
      int idx = tid + l * 512;
      int r = idx >> 3, q = idx & 7;
      int tok = slist[r];
      float4 v = make_float4(0.f, 0.f, 0.f, 0.f);
      if (tok >= 0) v = *(const float4*)(E + (size_t)tok * HDIM + q * 4);
      uint2 u01 = splitpair(v.x, v.y), u23 = splitpair(v.z, v.w);
      *(uint4*)(Ab + r * RB + q * 16) = make_uint4(u01.x, u01.y, u23.x, u23.y);
    }
    char* Bb = sm + F1_B0;
#pragma unroll
    for (int l = 0; l < 2; l++) {
      int idx = tid + l * 512;
      int nr = idx >> 3, u = idx & 7;
      cpa16(Bb + nr * RB + u * 16, g_w1p + (size_t)(col0 + nr) * 128 + u * 2);
    }
    CP_COMMIT;
  }

#pragma unroll 1
  for (int ch = 0; ch < 8; ch++) {
    char* Ab = sm + ((ch & 1) ? F1_A1 : F1_A0);
    char* Bb = sm + ((ch & 1) ? F1_B1 : F1_B0);
    char* An = sm + ((ch & 1) ? F1_A0 : F1_A1);
    char* Bn = sm + ((ch & 1) ? F1_B0 : F1_B1);
    CP_WAIT0;
    __syncthreads();
    const bool more = (ch + 1) < 8;
    float4 pre[2];
    if (more) {
#pragma unroll
      for (int l = 0; l < 2; l++) {
        int idx = tid + l * 512;
        int nr = idx >> 3, u = idx & 7;
        cpa16(Bn + nr * RB + u * 16,
              g_w1p + (size_t)(col0 + nr) * 128 + (ch + 1) * 16 + u * 2);
      }
      CP_COMMIT;
#pragma unroll
      for (int l = 0; l < 2; l++) {
        int idx = tid + l * 512;
        int r = idx >> 3, q = idx & 7;
        int tok = slist[r];
        pre[l] = make_float4(0.f, 0.f, 0.f, 0.f);
        if (tok >= 0)
          pre[l] = *(const float4*)(E + (size_t)tok * HDIM + (ch + 1) * 32 + q * 4);
      }
    }
#pragma unroll
    for (int h = 0; h < 2; h++) {
      uint2 bf0[4], bf1[4];
#pragma unroll
      for (int nt = 0; nt < 4; nt++) {
        char* bp = Bb + (wn * 32 + nt * 8 + gr) * RB + (h * 8 + tc) * 8;
        bf0[nt] = *(uint2*)bp;
        bf1[nt] = *(uint2*)(bp + 32);
      }
#pragma unroll
      for (int mt = 0; mt < 2; mt++) {
        char* ap = Ab + (wm * 32 + mt * 16 + gr) * RB + (h * 8 + tc) * 8;
        uint2 a0 = *(uint2*)ap;
        uint2 a1 = *(uint2*)(ap + 8 * RB);
        uint2 a2 = *(uint2*)(ap + 32);
        uint2 a3 = *(uint2*)(ap + 8 * RB + 32);
#pragma unroll
        for (int nt = 0; nt < 4; nt++) {
          mma16(acc0[mt][nt], a0.x, a1.x, a2.x, a3.x, bf0[nt].x, bf1[nt].x);
          mma16(acc1[mt][nt], a0.x, a1.x, a2.x, a3.x, bf0[nt].y, bf1[nt].y);
          mma16(acc1[mt][nt], a0.y, a1.y, a2.y, a3.y, bf0[nt].x, bf1[nt].x);
        }
      }
    }
    if (more) {
#pragma unroll
      for (int l = 0; l < 2; l++) {
        int idx = tid + l * 512;
        int r = idx >> 3, q = idx & 7;
        uint2 u01 = splitpair(pre[l].x, pre[l].y), u23 = splitpair(pre[l].z, pre[l].w);
        *(uint4*)(An + r * RB + q * 16) = make_uint4(u01.x, u01.y, u23.x, u23.y);
      }
    }
    __syncthreads();
  }

  // epilogue: combine, bias+relu, pre-split store (compact rows)
#pragma unroll
  for (int mt = 0; mt < 2; mt++) {
#pragma unroll
    for (int nt = 0; nt < 4; nt++) {
      int c0 = col0 + wn * 32 + nt * 8 + tc * 2;
      float bb0 = b1[c0], bb1 = b1[c0 + 1];
#pragma unroll
      for (int i = 0; i < 2; i++) {
        int row = row0 + wm * 32 + mt * 16 + gr + i * 8;
        if (row < cnt) {
          float v0 = fmaxf(acc0[mt][nt][i * 2] + acc1[mt][nt][i * 2] * INV2048 + bb0, 0.f);
          float v1 = fmaxf(acc0[mt][nt][i * 2 + 1] + acc1[mt][nt][i * 2 + 1] * INV2048 + bb1, 0.f);
          g_t1p[(size_t)row * 256 + (c0 >> 1)] = splitpair(v0, v1);
        }
      }
    }
  }
}

// ============================================================================
// FFN2 over compact rows. Block 64x256 (full row), 512 thr.
// ============================================================================
#define F2_A0 0
#define F2_A1 10240
#define F2_B0 20480
#define F2_B1 61440
#define F2_PAR 102400
#define F2_PS  (F2_PAR + 4096)
#define F2_PS2 (F2_PS + 2048)
#define F2_PPG (F2_PS2 + 2048)
#define F2_MU  (F2_PPG + 2048)
#define F2_RS  (F2_MU + 256)
#define F2_SS  (F2_RS + 256)
#define F2_SMEM (F2_SS + 16)

__global__ __launch_bounds__(512) void k_ffn2(const float* __restrict__ E,
                                              const float* __restrict__ b2,
                                              const float* __restrict__ ln_g,
                                              const float* __restrict__ ln_b,
                                              const float* __restrict__ gate_w,
                                              const float* __restrict__ gate_b) {
  extern __shared__ __align__(16) char sm[];
  __shared__ int slist[64];
  float* sb2 = (float*)(sm + F2_PAR);
  float* slg = sb2 + 256;
  float* slb = slg + 256;
  float* sgg = slb + 256;
  float* pS = (float*)(sm + F2_PS);
  float* pS2 = (float*)(sm + F2_PS2);
  float* pPG = (float*)(sm + F2_PPG);
  float* sMU = (float*)(sm + F2_MU);
  float* sRS = (float*)(sm + F2_RS);
  float* sS = (float*)(sm + F2_SS);
  const int tid = threadIdx.x, lane = tid & 31, wid = tid >> 5;
  const int gr = lane >> 2, tc = lane & 3;
  const int wm = wid & 1, wn = wid >> 1;
  const int row0 = blockIdx.x * 64;

  const int cnt = g_count;
  if (row0 >= cnt) return;
  if (tid < 64) slist[tid] = (row0 + tid < cnt) ? g_list[row0 + tid] : -1;

  if (tid < 256) {
    float lg = ln_g[tid], lb = ln_b[tid], gw = gate_w[tid];
    sb2[tid] = b2[tid];
    slg[tid] = lg;
    slb[tid] = lb;
    sgg[tid] = lg * gw;
  }

  float acc0[2][4][4], acc1[2][4][4];
#pragma unroll
  for (int mt = 0; mt < 2; mt++)
#pragma unroll
    for (int nt = 0; nt < 4; nt++)
#pragma unroll
      for (int r = 0; r < 4; r++) { acc0[mt][nt][r] = 0.f; acc1[mt][nt][r] = 0.f; }

  // prologue: chunk 0
  {
    int nr = tid >> 3, u = tid & 7;
    cpa16(sm + F2_A0 + nr * RB + u * 16, g_t1p + (size_t)(row0 + nr) * 256 + u * 2);
#pragma unroll
    for (int l = 0; l < 4; l++) {
      int idx = tid + l * 512;
      int br = idx >> 3, bu = idx & 7;
      cpa16(sm + F2_B0 + br * RB + bu * 16, g_w2p + (size_t)br * 256 + bu * 2);
    }
    CP_COMMIT;
  }

#pragma unroll 1
  for (int ch = 0; ch < 16; ch++) {
    char* Ab = sm + ((ch & 1) ? F2_A1 : F2_A0);
    char* Bb = sm + ((ch & 1) ? F2_B1 : F2_B0);
    char* An = sm + ((ch & 1) ? F2_A0 : F2_A1);
    char* Bn = sm + ((ch & 1) ? F2_B0 : F2_B1);
    CP_WAIT0;
    __syncthreads();
    if (ch + 1 < 16) {
      int nr = tid >> 3, u = tid & 7;
      cpa16(An + nr * RB + u * 16,
            g_t1p + (size_t)(row0 + nr) * 256 + (ch + 1) * 16 + u * 2);
#pragma unroll
      for (int l = 0; l < 4; l++) {
        int idx = tid + l * 512;
        int br = idx >> 3, bu = idx & 7;
        cpa16(Bn + br * RB + bu * 16, g_w2p + (size_t)br * 256 + (ch + 1) * 16 + bu * 2);
      }
      CP_COMMIT;
    }
#pragma unroll
    for (int h = 0; h < 2; h++) {
      uint2 bf0[4], bf1[4];
#pragma unroll
      for (int nt = 0; nt < 4; nt++) {
        char* bp = Bb + (wn * 32 + nt * 8 + gr) * RB + (h * 8 + tc) * 8;
        bf0[nt] = *(uint2*)bp;
        bf1[nt] = *(uint2*)(bp + 32);
      }
#pragma unroll
      for (int mt = 0; mt < 2; mt++) {
        char* ap = Ab + (wm * 32 + mt * 16 + gr) * RB + (h * 8 + tc) * 8;
        uint2 a0 = *(uint2*)ap;
        uint2 a1 = *(uint2*)(ap + 8 * RB);
        uint2 a2 = *(uint2*)(ap + 32);
        uint2 a3 = *(uint2*)(ap + 8 * RB + 32);
#pragma unroll
        for (int nt = 0; nt < 4; nt++) {
          mma16(acc0[mt][nt], a0.x, a1.x, a2.x, a3.x, bf0[nt].x, bf1[nt].x);
          mma16(acc1[mt][nt], a0.x, a1.x, a2.x, a3.x, bf0[nt].y, bf1[nt].y);
          mma16(acc1[mt][nt], a0.y, a1.y, a2.y, a3.y, bf0[nt].x, bf1[nt].x);
        }
      }
    }
    __syncthreads();
  }

  if (wid == 0) {
    float a = 0.f, b = 0.f;
#pragma unroll
    for (int i = 0; i < 8; i++) {
      a += sgg[lane + 32 * i];
      b += slb[lane + 32 * i] * gate_w[lane + 32 * i];
    }
    a = wred_sum(a);
    b = wred_sum(b);
    if (lane == 0) { sS[0] = a; sS[1] = b + gate_b[0]; }
  }

  // pass 1: combine + residual, accumulate row stats
#pragma unroll
  for (int mt = 0; mt < 2; mt++) {
#pragma unroll
    for (int i = 0; i < 2; i++) {
      int rl = wm * 32 + mt * 16 + gr + i * 8;
      int tok = slist[rl];
      bool valid = tok >= 0;
      float s = 0.f, sq = 0.f, pg = 0.f;
#pragma unroll
      for (int nt = 0; nt < 4; nt++) {
        int c0 = wn * 32 + nt * 8 + tc * 2;
        float2 ev = make_float2(0.f, 0.f);
        if (valid) ev = *(const float2*)(E + (size_t)tok * HDIM + c0);
        float x0 = acc0[mt][nt][i * 2] + acc1[mt][nt][i * 2] * INV2048 + sb2[c0] + ev.x;
        float x1 = acc0[mt][nt][i * 2 + 1] + acc1[mt][nt][i * 2 + 1] * INV2048 + sb2[c0 + 1] + ev.y;
        acc0[mt][nt][i * 2] = x0;
        acc0[mt][nt][i * 2 + 1] = x1;
        s += x0 + x1;
        sq += x0 * x0 + x1 * x1;
        pg += x0 * sgg[c0] + x1 * sgg[c0 + 1];
      }
      s += __shfl_xor_sync(0xffffffffu, s, 1);
      s += __shfl_xor_sync(0xffffffffu, s, 2);
      sq += __shfl_xor_sync(0xffffffffu, sq, 1);
      sq += __shfl_xor_sync(0xffffffffu, sq, 2);
      pg += __shfl_xor_sync(0xffffffffu, pg, 1);
      pg += __shfl_xor_sync(0xffffffffu, pg, 2);
      if (tc == 0) {
        pS[wn * 64 + rl] = s;
        pS2[wn * 64 + rl] = sq;
        pPG[wn * 64 + rl] = pg;
      }
    }
  }
  __syncthreads();
  if (tid < 64) {
    float s = 0.f, sq = 0.f, pg = 0.f;
#pragma unroll
    for (int w = 0; w < 8; w++) {
      s += pS[w * 64 + tid];
      sq += pS2[w * 64 + tid];
      pg += pPG[w * 64 + tid];
    }
    float mu = s * (1.f / 256.f);
    float var = sq * (1.f / 256.f) - mu * mu;
    float rs = rsqrtf(var + 1e-5f);
    sMU[tid] = mu;
    sRS[tid] = rs;
    int rg = row0 + tid;
    if (rg < cnt) g_score[rg] = rs * (pg - mu * sS[0]) + sS[1];
  }
  __syncthreads();

  // pass 2: normalize + store hidden (compact rows)
#pragma unroll
  for (int mt = 0; mt < 2; mt++) {
#pragma unroll
    for (int i = 0; i < 2; i++) {
      int rl = wm * 32 + mt * 16 + gr + i * 8;
      int rg = row0 + rl;
      if (rg >= cnt) continue;
      float mu = sMU[rl], rs = sRS[rl];
#pragma unroll
      for (int nt = 0; nt < 4; nt++) {
        int c0 = wn * 32 + nt * 8 + tc * 2;
        float2 o;
        o.x = (acc0[mt][nt][i * 2] - mu) * rs * slg[c0] + slb[c0];
        o.y = (acc0[mt][nt][i * 2 + 1] - mu) * rs * slg[c0 + 1] + slb[c0 + 1];
        *(float2*)(g_hidden + (size_t)rg * HDIM + c0) = o;
      }
    }
  }
}

// ---------------- Pass 3: per-batch top-512 (bitonic sort 4096) ----------------
__global__ __launch_bounds__(1024) void k_topk(const int* __restrict__ seq) {
  __shared__ float sv[4096];
  __shared__ int si[4096];
  const int b = blockIdx.x;
  const int tid = threadIdx.x;

  for (int i = tid; i < 4096; i += 1024) {
    if (i < TCAND) {
      int tok = seq[b * SEQT + i];
      sv[i] = g_score[g_comp[tok]];
      si[i] = i;
    } else {
      sv[i] = -INFINITY;
      si[i] = i;
    }
  }
  __syncthreads();

  for (int k = 2; k <= 4096; k <<= 1) {
    for (int j = k >> 1; j > 0; j >>= 1) {
      for (int t = tid; t < 2048; t += 1024) {
        int i = ((t & ~(j - 1)) << 1) | (t & (j - 1));
        int p = i | j;
        float v1 = sv[i], v2 = sv[p];
        int i1 = si[i], i2 = si[p];
        bool gt = (v1 > v2) || (v1 == v2 && i1 < i2);
        bool desc = ((i & k) == 0);
        if (desc ? !gt : gt) { sv[i] = v2; sv[p] = v1; si[i] = i2; si[p] = i1; }
      }
      __syncthreads();
    }
  }
  for (int m = tid; m < MSEL; m += 1024)
    g_mem_tok[b * MSEL + m] = g_comp[seq[b * SEQT + si[m]]];
}

// ---------------- Pass 4: query proj + attention + context ----------------
__global__ __launch_bounds__(1024) void k_attn(const int* __restrict__ seq,
                                               const float* __restrict__ qa_w,
                                               const float* __restrict__ qa_b,
                                               const float* __restrict__ qr_w,
                                               const float* __restrict__ qr_b) {
  __shared__ float hq[HDIM], q1[HDIM], q2[HDIM];
  __shared__ float att[MSEL];
  __shared__ int stok[MSEL];
  __shared__ float part[4][HDIM];
  __shared__ float red[32];
  __shared__ float sred[2];
  const int b = blockIdx.x;
  const int tid = threadIdx.x;
  const int lane = tid & 31, w = tid >> 5;
  const int o = tid & 255, p = tid >> 8;

  if (tid < 256) {
    int cq = g_comp[seq[b * SEQT + (SEQT - 2)]];
    hq[tid] = g_hidden[(size_t)cq * HDIM + tid];
  }
  if (tid < MSEL) stok[tid] = g_mem_tok[b * MSEL + tid];
  __syncthreads();

  {
    float s = 0.f;
#pragma unroll 8
    for (int h = p * 64; h < p * 64 + 64; h++) s = fmaf(hq[h], qa_w[h * HDIM + o], s);
    part[p][o] = s;
  }
  __syncthreads();
  if (tid < 256) q1[tid] = qa_b[tid] + part[0][tid] + part[1][tid] + part[2][tid] + part[3][tid];
  __syncthreads();
  {
    float s = 0.f;
#pragma unroll 8
    for (int h = p * 64; h < p * 64 + 64; h++) s = fmaf(q1[h], qr_w[h * HDIM + o], s);
    part[p][o] = s;
  }
  __syncthreads();
  if (tid < 256) q2[tid] = qr_b[tid] + part[0][tid] + part[1][tid] + part[2][tid] + part[3][tid];
  __syncthreads();

#pragma unroll 2
  for (int t = 0; t < 16; t++) {
    int m = w * 16 + t;
    const float* row = g_hidden + (size_t)stok[m] * HDIM;
    float s = 0.f;
#pragma unroll
    for (int c = 0; c < 8; c++) s = fmaf(row[lane + 32 * c], q2[lane + 32 * c], s);
    s = wred_sum(s);
    if (lane == 0) att[m] = s;
  }
  __syncthreads();

  float v = (tid < MSEL) ? att[tid] : -INFINITY;
  float mx = v;
#pragma unroll
  for (int off = 16; off > 0; off >>= 1) mx = fmaxf(mx, __shfl_xor_sync(0xffffffffu, mx, off));
  if (lane == 0) red[w] = mx;
  __syncthreads();
  if (w == 0) {
    float m2 = red[lane];
#pragma unroll
    for (int off = 16; off > 0; off >>= 1) m2 = fmaxf(m2, __shfl_xor_sync(0xffffffffu, m2, off));
    if (lane == 0) sred[0] = m2;
  }
  __syncthreads();
  float gmx = sred[0];
  float e = (tid < MSEL) ? expf(v - gmx) : 0.f;
  if (tid < MSEL) att[tid] = e;
  float ssum = wred_sum(e);
  __syncthreads();
  if (lane == 0) red[w] = ssum;
  __syncthreads();
  if (w == 0) {
    float s2 = red[lane];
    s2 = wred_sum(s2);
    if (lane == 0) sred[1] = s2;
  }
  __syncthreads();
  float inv = 1.f / sred[1];

  {
    float c = 0.f;
#pragma unroll 4
    for (int m = p * 128; m < p * 128 + 128; m++)
      c = fmaf(att[m], g_hidden[(size_t)stok[m] * HDIM + o], c);
    part[p][o] = c;
  }
  __syncthreads();
  if (tid < 256)
    g_ctx[b * HDIM + tid] = (part[0][tid] + part[1][tid] + part[2][tid] + part[3][tid]) * inv;
}

// ---------------- Pass 5: out = ctx @ out_w + out_b ----------------
__global__ __launch_bounds__(256) void k_out(const float* __restrict__ Wo,
                                             const float* __restrict__ bo,
                                             float* __restrict__ out) {
  __shared__ float cs[NBATCH * HDIM];
  const int tid = threadIdx.x;
  for (int i = tid; i < NBATCH * HDIM; i += 256) cs[i] = g_ctx[i];
  __syncthreads();
  int v = blockIdx.x * 256 + tid;
  if (v >= VOCAB) return;
  float accv[NBATCH];
  float bias = bo[v];
#pragma unroll
  for (int b = 0; b < NBATCH; b++) accv[b] = bias;
#pragma unroll 8
  for (int h = 0; h < HDIM; h++) {
    float wv = Wo[(size_t)h * VOCAB + v];
#pragma unroll
    for (int b = 0; b < NBATCH; b++) accv[b] = fmaf(cs[b * HDIM + h], wv, accv[b]);
  }
#pragma unroll
  for (int b = 0; b < NBATCH; b++) out[(size_t)b * VOCAB + v] = accv[b];
}

// ---------------- launch ----------------
extern "C" void kernel_launch(void* const* d_in, const int* in_sizes, int n_in,
                              void* d_out, int out_size) {
  const int* seq = (const int*)d_in[0];
  const float* embed = (const float*)d_in[1];
  const float* W1 = (const float*)d_in[2];
  const float* b1 = (const float*)d_in[3];
  const float* W2 = (const float*)d_in[4];
  const float* b2 = (const float*)d_in[5];
  const float* ln_g = (const float*)d_in[6];
  const float* ln_b = (const float*)d_in[7];
  const float* gate_w = (const float*)d_in[8];
  const float* gate_b = (const float*)d_in[9];
  const float* qa_w = (const float*)d_in[10];
  const float* qa_b = (const float*)d_in[11];
  const float* qr_w = (const float*)d_in[12];
  const float* qr_b = (const float*)d_in[13];
  const float* out_w = (const float*)d_in[14];
  const float* out_b = (const float*)d_in[15];
  float* out = (float*)d_out;

  cudaFuncSetAttribute(k_ffn1, cudaFuncAttributeMaxDynamicSharedMemorySize, F1_SMEM);
  cudaFuncSetAttribute(k_ffn2, cudaFuncAttributeMaxDynamicSharedMemorySize, F2_SMEM);

  k_clear<<<(VOCAB + 1023) / 1024, 1024>>>();
  k_mark<<<(NBATCH * (TCAND + 1) + 1023) / 1024, 1024>>>(seq);
  k_prep<<<512, 256>>>(W1, W2);
  dim3 g1((VOCAB + 127) / 128, 4);
  k_ffn1<<<g1, 512, F1_SMEM>>>(embed, b1);
  k_ffn2<<<(VOCAB + 63) / 64, 512, F2_SMEM>>>(embed, b2, ln_g, ln_b, gate_w, gate_b);
  k_topk<<<NBATCH, 1024>>>(seq);
  k_attn<<<NBATCH, 1024>>>(seq, qa_w, qa_b, qr_w, qr_b);
  k_out<<<(VOCAB + 255) / 256, 256>>>(out_w, out_b, out);
}

// round 8
// speedup vs baseline: 3.0515x; 1.0051x over previous
#include <cuda_runtime.h>
#include <cuda_fp16.h>
#include <math.h>
#include <stdint.h>

#define VOCAB  50257
#define VPAD   50304
#define HDIM   256
#define FDIM   512
#define NBATCH 16
#define SEQT   4096
#define TCAND  4093
#define MSEL   512
#define INV2048 (1.0f / 2048.0f)

// ---------------- device scratch ----------------
// pair format: uint2 = { half2(hi(k), hi(k+1)), half2(lo(k)*2048, lo(k+1)*2048) }
__device__ uint2 g_t1p[(size_t)VPAD * 256];   // t1 pre-split, [compact_row][kpair]
__device__ uint2 g_w1p[FDIM * 128];           // W1 pre-split, [n][kpair]
__device__ uint2 g_w2p[HDIM * 256];           // W2 pre-split, [n][kpair]
__device__ float g_hidden[(size_t)VPAD * HDIM];  // per compact row
__device__ float g_score[VPAD];                  // per compact row
__device__ int   g_mem_tok[NBATCH * MSEL];       // compact ids
__device__ float g_ctx[NBATCH * HDIM];
// compaction
__device__ int g_flag[VOCAB];
__device__ int g_comp[VOCAB];
__device__ int g_list[VPAD];
__device__ int g_count;

// ---------------- helpers ----------------
__device__ __forceinline__ float wred_sum(float v) {
#pragma unroll
  for (int o = 16; o > 0; o >>= 1) v += __shfl_xor_sync(0xffffffffu, v, o);
  return v;
}
__device__ __forceinline__ uint2 splitpair(float x0, float x1) {
  __half h0 = __float2half_rn(x0);
  __half h1 = __float2half_rn(x1);
  float r0 = (x0 - __half2float(h0)) * 2048.f;
  float r1 = (x1 - __half2float(h1)) * 2048.f;
  __half2 hp = __halves2half2(h0, h1);
  __half2 lp = __floats2half2_rn(r0, r1);
  uint2 u;
  u.x = *(uint32_t*)&hp;
  u.y = *(uint32_t*)&lp;
  return u;
}
__device__ __forceinline__ void mma16(float* d, uint32_t a0, uint32_t a1, uint32_t a2,
                                      uint32_t a3, uint32_t b0, uint32_t b1) {
  asm volatile(
      "mma.sync.aligned.m16n8k16.row.col.f32.f16.f16.f32 "
      "{%0,%1,%2,%3}, {%4,%5,%6,%7}, {%8,%9}, {%0,%1,%2,%3};"
      : "+f"(d[0]), "+f"(d[1]), "+f"(d[2]), "+f"(d[3])
      : "r"(a0), "r"(a1), "r"(a2), "r"(a3), "r"(b0), "r"(b1));
}
__device__ __forceinline__ void cpa16(void* smem_dst, const void* gsrc) {
  uint32_t s = (uint32_t)__cvta_generic_to_shared(smem_dst);
  asm volatile("cp.async.cg.shared.global [%0], [%1], 16;" :: "r"(s), "l"(gsrc));
}
#define CP_COMMIT asm volatile("cp.async.commit_group;")
#define CP_WAIT0  asm volatile("cp.async.wait_group 0;" ::: "memory")

#define RB 160  // smem row stride bytes (payload 128 = 16 pairs x 8B), conflict-free

// ---------------- compaction ----------------
__global__ __launch_bounds__(1024) void k_clear() {
  int i = blockIdx.x * 1024 + threadIdx.x;
  if (i < VOCAB) {
    g_flag[i] = 0;
    g_comp[i] = 0;
  }
  if (i == 0) g_count = 0;
}
// mark tokens from seq[:, 0:4093] and seq[:, 4094]; assign compact ids
__global__ __launch_bounds__(1024) void k_mark(const int* __restrict__ seq) {
  int i = blockIdx.x * 1024 + threadIdx.x;
  if (i >= NBATCH * (TCAND + 1)) return;
  int b = i / (TCAND + 1);
  int j = i - b * (TCAND + 1);
  int pos = (j < TCAND) ? j : (SEQT - 2);
  int tok = seq[b * SEQT + pos];
  if (atomicExch(&g_flag[tok], 1) == 0) {
    int id = atomicAdd(&g_count, 1);
    g_comp[tok] = id;
    g_list[id] = tok;
  }
}

// ---------------- prep: pre-split W1, W2 into pair format ----------------
__global__ __launch_bounds__(256) void k_prep(const float* __restrict__ W1,
                                              const float* __restrict__ W2) {
  int g = blockIdx.x * 256 + threadIdx.x;
  if (g < FDIM * 128) {
    int n = g >> 7, c = g & 127;
    g_w1p[n * 128 + c] = splitpair(W1[(2 * c) * FDIM + n], W1[(2 * c + 1) * FDIM + n]);
  } else {
    g -= FDIM * 128;
    if (g < HDIM * 256) {
      int n = g >> 8, c = g & 255;
      g_w2p[n * 256 + c] = splitpair(W2[(2 * c) * HDIM + n], W2[(2 * c + 1) * HDIM + n]);
    }
  }
}

// ============================================================================
// FFN1: t1 = relu(E[list] @ W1 + b1) over compact rows. Block 128x128, 512 thr.
// ============================================================================
#define F1_A0 0
#define F1_A1 20480
#define F1_B0 40960
#define F1_B1 61440
#define F1_SMEM 81920

__global__ __launch_bounds__(512) void k_ffn1(const float* __restrict__ E,
                                              const float* __restrict__ b1) {
  extern __shared__ __align__(16) char sm[];
  __shared__ int slist[128];
  const int tid = threadIdx.x, lane = tid & 31, wid = tid >> 5;
  const int gr = lane >> 2, tc = lane & 3;
  const int wm = wid & 3, wn = wid >> 2;
  const int row0 = blockIdx.x * 128, col0 = blockIdx.y * 128;

  const int cnt = g_count;
  if (row0 >= cnt) return;
  if (tid < 128) slist[tid] = (row0 + tid < cnt) ? g_list[row0 + tid] : -1;
  __syncthreads();

  float acc0[2][4][4], acc1[2][4][4];
#pragma unroll
  for (int mt = 0; mt < 2; mt++)
#pragma unroll
    for (int nt = 0; nt < 4; nt++)
#pragma unroll
      for (int r = 0; r < 4; r++) { acc0[mt][nt][r] = 0.f; acc1[mt][nt][r] = 0.f; }

  // prologue: stage chunk 0
  {
    char* Ab = sm + F1_A0;
#pragma unroll
    for (int l = 0; l < 2; l++) {
      int idx = tid + l * 512;
      int r = idx >> 3, q = idx & 7;
      int tok = slist[r];
      float4 v = make_float4(0.f, 0.f, 0.f, 0.f);
      if (tok >= 0) v = *(const float4*)(E + (size_t)tok * HDIM + q * 4);
      uint2 u01 = splitpair(v.x, v.y), u23 = splitpair(v.z, v.w);
      *(uint4*)(Ab + r * RB + q * 16) = make_uint4(u01.x, u01.y, u23.x, u23.y);
    }
    char* Bb = sm + F1_B0;
#pragma unroll
    for (int l = 0; l < 2; l++) {
      int idx = tid + l * 512;
      int nr = idx >> 3, u = idx & 7;
      cpa16(Bb + nr * RB + u * 16, g_w1p + (size_t)(col0 + nr) * 128 + u * 2);
    }
    CP_COMMIT;
  }

#pragma unroll 1
  for (int ch = 0; ch < 8; ch++) {
    char* Ab = sm + ((ch & 1) ? F1_A1 : F1_A0);
    char* Bb = sm + ((ch & 1) ? F1_B1 : F1_B0);
    char* An = sm + ((ch & 1) ? F1_A0 : F1_A1);
    char* Bn = sm + ((ch & 1) ? F1_B0 : F1_B1);
    CP_WAIT0;
    __syncthreads();
    const bool more = (ch + 1) < 8;
    float4 pre[2];
    if (more) {
#pragma unroll
      for (int l = 0; l < 2; l++) {
        int idx = tid + l * 512;
        int nr = idx >> 3, u = idx & 7;
        cpa16(Bn + nr * RB + u * 16,
              g_w1p + (size_t)(col0 + nr) * 128 + (ch + 1) * 16 + u * 2);
      }
      CP_COMMIT;
#pragma unroll
      for (int l = 0; l < 2; l++) {
        int idx = tid + l * 512;
        int r = idx >> 3, q = idx & 7;
        int tok = slist[r];
        pre[l] = make_float4(0.f, 0.f, 0.f, 0.f);
        if (tok >= 0)
          pre[l] = *(const float4*)(E + (size_t)tok * HDIM + (ch + 1) * 32 + q * 4);
      }
    }
#pragma unroll
    for (int h = 0; h < 2; h++) {
      uint2 bf0[4], bf1[4];
#pragma unroll
      for (int nt = 0; nt < 4; nt++) {
        char* bp = Bb + (wn * 32 + nt * 8 + gr) * RB + (h * 8 + tc) * 8;
        bf0[nt] = *(uint2*)bp;
        bf1[nt] = *(uint2*)(bp + 32);
      }
#pragma unroll
      for (int mt = 0; mt < 2; mt++) {
        char* ap = Ab + (wm * 32 + mt * 16 + gr) * RB + (h * 8 + tc) * 8;
        uint2 a0 = *(uint2*)ap;
        uint2 a1 = *(uint2*)(ap + 8 * RB);
        uint2 a2 = *(uint2*)(ap + 32);
        uint2 a3 = *(uint2*)(ap + 8 * RB + 32);
#pragma unroll
        for (int nt = 0; nt < 4; nt++) {
          mma16(acc0[mt][nt], a0.x, a1.x, a2.x, a3.x, bf0[nt].x, bf1[nt].x);
          mma16(acc1[mt][nt], a0.x, a1.x, a2.x, a3.x, bf0[nt].y, bf1[nt].y);
          mma16(acc1[mt][nt], a0.y, a1.y, a2.y, a3.y, bf0[nt].x, bf1[nt].x);
        }
      }
    }
    if (more) {
#pragma unroll
      for (int l = 0; l < 2; l++) {
        int idx = tid + l * 512;
        int r = idx >> 3, q = idx & 7;
        uint2 u01 = splitpair(pre[l].x, pre[l].y), u23 = splitpair(pre[l].z, pre[l].w);
        *(uint4*)(An + r * RB + q * 16) = make_uint4(u01.x, u01.y, u23.x, u23.y);
      }
    }
    __syncthreads();
  }

  // epilogue: combine, bias+relu, pre-split store (compact rows)
#pragma unroll
  for (int mt = 0; mt < 2; mt++) {
#pragma unroll
    for (int nt = 0; nt < 4; nt++) {
      int c0 = col0 + wn * 32 + nt * 8 + tc * 2;
      float bb0 = b1[c0], bb1 = b1[c0 + 1];
#pragma unroll
      for (int i = 0; i < 2; i++) {
        int row = row0 + wm * 32 + mt * 16 + gr + i * 8;
        if (row < cnt) {
          float v0 = fmaxf(acc0[mt][nt][i * 2] + acc1[mt][nt][i * 2] * INV2048 + bb0, 0.f);
          float v1 = fmaxf(acc0[mt][nt][i * 2 + 1] + acc1[mt][nt][i * 2 + 1] * INV2048 + bb1, 0.f);
          g_t1p[(size_t)row * 256 + (c0 >> 1)] = splitpair(v0, v1);
        }
      }
    }
  }
}

// ============================================================================
// FFN2 over compact rows. Block 64x256 (full row), 512 thr.
// ============================================================================
#define F2_A0 0
#define F2_A1 10240
#define F2_B0 20480
#define F2_B1 61440
#define F2_PAR 102400
#define F2_PS  (F2_PAR + 4096)
#define F2_PS2 (F2_PS + 2048)
#define F2_PPG (F2_PS2 + 2048)
#define F2_MU  (F2_PPG + 2048)
#define F2_RS  (F2_MU + 256)
#define F2_SS  (F2_RS + 256)
#define F2_SMEM (F2_SS + 16)

__global__ __launch_bounds__(512) void k_ffn2(const float* __restrict__ E,
                                              const float* __restrict__ b2,
                                              const float* __restrict__ ln_g,
                                              const float* __restrict__ ln_b,
                                              const float* __restrict__ gate_w,
                                              const float* __restrict__ gate_b) {
  extern __shared__ __align__(16) char sm[];
  __shared__ int slist[64];
  float* sb2 = (float*)(sm + F2_PAR);
  float* slg = sb2 + 256;
  float* slb = slg + 256;
  float* sgg = slb + 256;
  float* pS = (float*)(sm + F2_PS);
  float* pS2 = (float*)(sm + F2_PS2);
  float* pPG = (float*)(sm + F2_PPG);
  float* sMU = (float*)(sm + F2_MU);
  float* sRS = (float*)(sm + F2_RS);
  float* sS = (float*)(sm + F2_SS);
  const int tid = threadIdx.x, lane = tid & 31, wid = tid >> 5;
  const int gr = lane >> 2, tc = lane & 3;
  const int wm = wid & 1, wn = wid >> 1;
  const int row0 = blockIdx.x * 64;

  const int cnt = g_count;
  if (row0 >= cnt) return;
  if (tid < 64) slist[tid] = (row0 + tid < cnt) ? g_list[row0 + tid] : -1;

  if (tid < 256) {
    float lg = ln_g[tid], lb = ln_b[tid], gw = gate_w[tid];
    sb2[tid] = b2[tid];
    slg[tid] = lg;
    slb[tid] = lb;
    sgg[tid] = lg * gw;
  }

  float acc0[2][4][4], acc1[2][4][4];
#pragma unroll
  for (int mt = 0; mt < 2; mt++)
#pragma unroll
    for (int nt = 0; nt < 4; nt++)
#pragma unroll
      for (int r = 0; r < 4; r++) { acc0[mt][nt][r] = 0.f; acc1[mt][nt][r] = 0.f; }

  // prologue: chunk 0
  {
    int nr = tid >> 3, u = tid & 7;
    cpa16(sm + F2_A0 + nr * RB + u * 16, g_t1p + (size_t)(row0 + nr) * 256 + u * 2);
#pragma unroll
    for (int l = 0; l < 4; l++) {
      int idx = tid + l * 512;
      int br = idx >> 3, bu = idx & 7;
      cpa16(sm + F2_B0 + br * RB + bu * 16, g_w2p + (size_t)br * 256 + bu * 2);
    }
    CP_COMMIT;
  }

#pragma unroll 1
  for (int ch = 0; ch < 16; ch++) {
    char* Ab = sm + ((ch & 1) ? F2_A1 : F2_A0);
    char* Bb = sm + ((ch & 1) ? F2_B1 : F2_B0);
    char* An = sm + ((ch & 1) ? F2_A0 : F2_A1);
    char* Bn = sm + ((ch & 1) ? F2_B0 : F2_B1);
    CP_WAIT0;
    __syncthreads();
    if (ch + 1 < 16) {
      int nr = tid >> 3, u = tid & 7;
      cpa16(An + nr * RB + u * 16,
            g_t1p + (size_t)(row0 + nr) * 256 + (ch + 1) * 16 + u * 2);
#pragma unroll
      for (int l = 0; l < 4; l++) {
        int idx = tid + l * 512;
        int br = idx >> 3, bu = idx & 7;
        cpa16(Bn + br * RB + bu * 16, g_w2p + (size_t)br * 256 + (ch + 1) * 16 + bu * 2);
      }
      CP_COMMIT;
    }
#pragma unroll
    for (int h = 0; h < 2; h++) {
      uint2 bf0[4], bf1[4];
#pragma unroll
      for (int nt = 0; nt < 4; nt++) {
        char* bp = Bb + (wn * 32 + nt * 8 + gr) * RB + (h * 8 + tc) * 8;
        bf0[nt] = *(uint2*)bp;
        bf1[nt] = *(uint2*)(bp + 32);
      }
#pragma unroll
      for (int mt = 0; mt < 2; mt++) {
        char* ap = Ab + (wm * 32 + mt * 16 + gr) * RB + (h * 8 + tc) * 8;
        uint2 a0 = *(uint2*)ap;
        uint2 a1 = *(uint2*)(ap + 8 * RB);
        uint2 a2 = *(uint2*)(ap + 32);
        uint2 a3 = *(uint2*)(ap + 8 * RB + 32);
#pragma unroll
        for (int nt = 0; nt < 4; nt++) {
          mma16(acc0[mt][nt], a0.x, a1.x, a2.x, a3.x, bf0[nt].x, bf1[nt].x);
          mma16(acc1[mt][nt], a0.x, a1.x, a2.x, a3.x, bf0[nt].y, bf1[nt].y);
          mma16(acc1[mt][nt], a0.y, a1.y, a2.y, a3.y, bf0[nt].x, bf1[nt].x);
        }
      }
    }
    __syncthreads();
  }

  if (wid == 0) {
    float a = 0.f, b = 0.f;
#pragma unroll
    for (int i = 0; i < 8; i++) {
      a += sgg[lane + 32 * i];
      b += slb[lane + 32 * i] * gate_w[lane + 32 * i];
    }
    a = wred_sum(a);
    b = wred_sum(b);
    if (lane == 0) { sS[0] = a; sS[1] = b + gate_b[0]; }
  }

  // pass 1: combine + residual, accumulate row stats
#pragma unroll
  for (int mt = 0; mt < 2; mt++) {
#pragma unroll
    for (int i = 0; i < 2; i++) {
      int rl = wm * 32 + mt * 16 + gr + i * 8;
      int tok = slist[rl];
      bool valid = tok >= 0;
      float s = 0.f, sq = 0.f, pg = 0.f;
#pragma unroll
      for (int nt = 0; nt < 4; nt++) {
        int c0 = wn * 32 + nt * 8 + tc * 2;
        float2 ev = make_float2(0.f, 0.f);
        if (valid) ev = *(const float2*)(E + (size_t)tok * HDIM + c0);
        float x0 = acc0[mt][nt][i * 2] + acc1[mt][nt][i * 2] * INV2048 + sb2[c0] + ev.x;
        float x1 = acc0[mt][nt][i * 2 + 1] + acc1[mt][nt][i * 2 + 1] * INV2048 + sb2[c0 + 1] + ev.y;
        acc0[mt][nt][i * 2] = x0;
        acc0[mt][nt][i * 2 + 1] = x1;
        s += x0 + x1;
        sq += x0 * x0 + x1 * x1;
        pg += x0 * sgg[c0] + x1 * sgg[c0 + 1];
      }
      s += __shfl_xor_sync(0xffffffffu, s, 1);
      s += __shfl_xor_sync(0xffffffffu, s, 2);
      sq += __shfl_xor_sync(0xffffffffu, sq, 1);
      sq += __shfl_xor_sync(0xffffffffu, sq, 2);
      pg += __shfl_xor_sync(0xffffffffu, pg, 1);
      pg += __shfl_xor_sync(0xffffffffu, pg, 2);
      if (tc == 0) {
        pS[wn * 64 + rl] = s;
        pS2[wn * 64 + rl] = sq;
        pPG[wn * 64 + rl] = pg;
      }
    }
  }
  __syncthreads();
  if (tid < 64) {
    float s = 0.f, sq = 0.f, pg = 0.f;
#pragma unroll
    for (int w = 0; w < 8; w++) {
      s += pS[w * 64 + tid];
      sq += pS2[w * 64 + tid];
      pg += pPG[w * 64 + tid];
    }
    float mu = s * (1.f / 256.f);
    float var = sq * (1.f / 256.f) - mu * mu;
    float rs = rsqrtf(var + 1e-5f);
    sMU[tid] = mu;
    sRS[tid] = rs;
    int rg = row0 + tid;
    if (rg < cnt) g_score[rg] = rs * (pg - mu * sS[0]) + sS[1];
  }
  __syncthreads();

  // pass 2: normalize + store hidden (compact rows)
#pragma unroll
  for (int mt = 0; mt < 2; mt++) {
#pragma unroll
    for (int i = 0; i < 2; i++) {
      int rl = wm * 32 + mt * 16 + gr + i * 8;
      int rg = row0 + rl;
      if (rg >= cnt) continue;
      float mu = sMU[rl], rs = sRS[rl];
#pragma unroll
      for (int nt = 0; nt < 4; nt++) {
        int c0 = wn * 32 + nt * 8 + tc * 2;
        float2 o;
        o.x = (acc0[mt][nt][i * 2] - mu) * rs * slg[c0] + slb[c0];
        o.y = (acc0[mt][nt][i * 2 + 1] - mu) * rs * slg[c0 + 1] + slb[c0 + 1];
        *(float2*)(g_hidden + (size_t)rg * HDIM + c0) = o;
      }
    }
  }
}

// ---------------- Pass 3: per-batch top-512 (bitonic sort 4096) ----------------
__global__ __launch_bounds__(1024) void k_topk(const int* __restrict__ seq) {
  __shared__ float sv[4096];
  __shared__ int si[4096];
  const int b = blockIdx.x;
  const int tid = threadIdx.x;

  for (int i = tid; i < 4096; i += 1024) {
    if (i < TCAND) {
      int tok = seq[b * SEQT + i];
      sv[i] = g_score[g_comp[tok]];
      si[i] = i;
    } else {
      sv[i] = -INFINITY;
      si[i] = i;
    }
  }
  __syncthreads();

  for (int k = 2; k <= 4096; k <<= 1) {
    for (int j = k >> 1; j > 0; j >>= 1) {
      for (int t = tid; t < 2048; t += 1024) {
        int i = ((t & ~(j - 1)) << 1) | (t & (j - 1));
        int p = i | j;
        float v1 = sv[i], v2 = sv[p];
        int i1 = si[i], i2 = si[p];
        bool gt = (v1 > v2) || (v1 == v2 && i1 < i2);
        bool desc = ((i & k) == 0);
        if (desc ? !gt : gt) { sv[i] = v2; sv[p] = v1; si[i] = i2; si[p] = i1; }
      }
      __syncthreads();
    }
  }
  for (int m = tid; m < MSEL; m += 1024)
    g_mem_tok[b * MSEL + m] = g_comp[seq[b * SEQT + si[m]]];
}

// ---------------- Pass 4: query proj + attention + context ----------------
__global__ __launch_bounds__(1024) void k_attn(const int* __restrict__ seq,
                                               const float* __restrict__ qa_w,
                                               const float* __restrict__ qa_b,
                                               const float* __restrict__ qr_w,
                                               const float* __restrict__ qr_b) {
  __shared__ float hq[HDIM], q1[HDIM], q2[HDIM];
  __shared__ float att[MSEL];
  __shared__ int stok[MSEL];
  __shared__ float part[4][HDIM];
  __shared__ float red[32];
  __shared__ float sred[2];
  const int b = blockIdx.x;
  const int tid = threadIdx.x;
  const int lane = tid & 31, w = tid >> 5;
  const int o = tid & 255, p = tid >> 8;

  if (tid < 256) {
    int cq = g_comp[seq[b * SEQT + (SEQT - 2)]];
    hq[tid] = g_hidden[(size_t)cq * HDIM + tid];
  }
  if (tid < MSEL) stok[tid] = g_mem_tok[b * MSEL + tid];
  __syncthreads();

  {
    float s = 0.f;
#pragma unroll 8
    for (int h = p * 64; h < p * 64 + 64; h++) s = fmaf(hq[h], qa_w[h * HDIM + o], s);
    part[p][o] = s;
  }
  __syncthreads();
  if (tid < 256) q1[tid] = qa_b[tid] + part[0][tid] + part[1][tid] + part[2][tid] + part[3][tid];
  __syncthreads();
  {
    float s = 0.f;
#pragma unroll 8
    for (int h = p * 64; h < p * 64 + 64; h++) s = fmaf(q1[h], qr_w[h * HDIM + o], s);
    part[p][o] = s;
  }
  __syncthreads();
  if (tid < 256) q2[tid] = qr_b[tid] + part[0][tid] + part[1][tid] + part[2][tid] + part[3][tid];
  __syncthreads();

#pragma unroll 2
  for (int t = 0; t < 16; t++) {
    int m = w * 16 + t;
    const float* row = g_hidden + (size_t)stok[m] * HDIM;
    float s = 0.f;
#pragma unroll
    for (int c = 0; c < 8; c++) s = fmaf(row[lane + 32 * c], q2[lane + 32 * c], s);
    s = wred_sum(s);
    if (lane == 0) att[m] = s;
  }
  __syncthreads();

  float v = (tid < MSEL) ? att[tid] : -INFINITY;
  float mx = v;
#pragma unroll
  for (int off = 16; off > 0; off >>= 1) mx = fmaxf(mx, __shfl_xor_sync(0xffffffffu, mx, off));
  if (lane == 0) red[w] = mx;
  __syncthreads();
  if (w == 0) {
    float m2 = red[lane];
#pragma unroll
    for (int off = 16; off > 0; off >>= 1) m2 = fmaxf(m2, __shfl_xor_sync(0xffffffffu, m2, off));
    if (lane == 0) sred[0] = m2;
  }
  __syncthreads();
  float gmx = sred[0];
  float e = (tid < MSEL) ? expf(v - gmx) : 0.f;
  if (tid < MSEL) att[tid] = e;
  float ssum = wred_sum(e);
  __syncthreads();
  if (lane == 0) red[w] = ssum;
  __syncthreads();
  if (w == 0) {
    float s2 = red[lane];
    s2 = wred_sum(s2);
    if (lane == 0) sred[1] = s2;
  }
  __syncthreads();
  float inv = 1.f / sred[1];

  {
    float c = 0.f;
#pragma unroll 4
    for (int m = p * 128; m < p * 128 + 128; m++)
      c = fmaf(att[m], g_hidden[(size_t)stok[m] * HDIM + o], c);
    part[p][o] = c;
  }
  __syncthreads();
  if (tid < 256)
    g_ctx[b * HDIM + tid] = (part[0][tid] + part[1][tid] + part[2][tid] + part[3][tid]) * inv;
}

// ---------------- Pass 5: out = ctx @ out_w + out_b ----------------
__global__ __launch_bounds__(256) void k_out(const float* __restrict__ Wo,
                                             const float* __restrict__ bo,
                                             float* __restrict__ out) {
  __shared__ float cs[NBATCH * HDIM];
  const int tid = threadIdx.x;
  for (int i = tid; i < NBATCH * HDIM; i += 256) cs[i] = g_ctx[i];
  __syncthreads();
  int v = blockIdx.x * 256 + tid;
  if (v >= VOCAB) return;
  float accv[NBATCH];
  float bias = bo[v];
#pragma unroll
  for (int b = 0; b < NBATCH; b++) accv[b] = bias;
#pragma unroll 8
  for (int h = 0; h < HDIM; h++) {
    float wv = Wo[(size_t)h * VOCAB + v];
#pragma unroll
    for (int b = 0; b < NBATCH; b++) accv[b] = fmaf(cs[b * HDIM + h], wv, accv[b]);
  }
#pragma unroll
  for (int b = 0; b < NBATCH; b++) out[(size_t)b * VOCAB + v] = accv[b];
}

// ---------------- launch ----------------
extern "C" void kernel_launch(void* const* d_in, const int* in_sizes, int n_in,
                              void* d_out, int out_size) {
  const int* seq = (const int*)d_in[0];
  const float* embed = (const float*)d_in[1];
  const float* W1 = (const float*)d_in[2];
  const float* b1 = (const float*)d_in[3];
  const float* W2 = (const float*)d_in[4];
  const float* b2 = (const float*)d_in[5];
  const float* ln_g = (const float*)d_in[6];
  const float* ln_b = (const float*)d_in[7];
  const float* gate_w = (const float*)d_in[8];
  const float* gate_b = (const float*)d_in[9];
  const float* qa_w = (const float*)d_in[10];
  const float* qa_b = (const float*)d_in[11];
  const float* qr_w = (const float*)d_in[12];
  const float* qr_b = (const float*)d_in[13];
  const float* out_w = (const float*)d_in[14];
  const float* out_b = (const float*)d_in[15];
  float* out = (float*)d_out;

  cudaFuncSetAttribute(k_ffn1, cudaFuncAttributeMaxDynamicSharedMemorySize, F1_SMEM);
  cudaFuncSetAttribute(k_ffn2, cudaFuncAttributeMaxDynamicSharedMemorySize, F2_SMEM);

  k_clear<<<(VOCAB + 1023) / 1024, 1024>>>();
  k_mark<<<(NBATCH * (TCAND + 1) + 1023) / 1024, 1024>>>(seq);
  k_prep<<<512, 256>>>(W1, W2);
  dim3 g1((VOCAB + 127) / 128, 4);
  k_ffn1<<<g1, 512, F1_SMEM>>>(embed, b1);
  k_ffn2<<<(VOCAB + 63) / 64, 512, F2_SMEM>>>(embed, b2, ln_g, ln_b, gate_w, gate_b);
  k_topk<<<NBATCH, 1024>>>(seq);
  k_attn<<<NBATCH, 1024>>>(seq, qa_w, qa_b, qr_w, qr_b);
  k_out<<<(VOCAB + 255) / 256, 256>>>(out_w, out_b, out);
}

// round 9
// speedup vs baseline: 3.2201x; 1.0552x over previous
#include <cuda_runtime.h>
#include <cuda_fp16.h>
#include <math.h>
#include <stdint.h>

#define VOCAB  50257
#define VPAD   50304
#define HDIM   256
#define FDIM   512
#define NBATCH 16
#define SEQT   4096
#define TCAND  4093
#define MSEL   512
#define INV2048 (1.0f / 2048.0f)

// ---------------- device scratch ----------------
// pair format: uint2 = { half2(hi(k), hi(k+1)), half2(lo(k)*2048, lo(k+1)*2048) }
__device__ uint2 g_t1p[(size_t)VPAD * 256];   // t1 pre-split, [compact_row][kpair]
__device__ uint2 g_w1p[FDIM * 128];           // W1 pre-split, [n][kpair]
__device__ uint2 g_w2p[HDIM * 256];           // W2 pre-split, [n][kpair]
__device__ float g_hidden[(size_t)VPAD * HDIM];  // per compact row
__device__ float g_score[VPAD];                  // per compact row
__device__ int   g_mem_tok[NBATCH * MSEL];       // compact ids (set; order deterministic)
__device__ float g_ctx[NBATCH * HDIM];
// compaction
__device__ int g_flag[VOCAB];
__device__ int g_comp[VOCAB];
__device__ int g_list[VPAD];
__device__ int g_count;

// ---------------- helpers ----------------
__device__ __forceinline__ float wred_sum(float v) {
#pragma unroll
  for (int o = 16; o > 0; o >>= 1) v += __shfl_xor_sync(0xffffffffu, v, o);
  return v;
}
__device__ __forceinline__ uint2 splitpair(float x0, float x1) {
  __half h0 = __float2half_rn(x0);
  __half h1 = __float2half_rn(x1);
  float r0 = (x0 - __half2float(h0)) * 2048.f;
  float r1 = (x1 - __half2float(h1)) * 2048.f;
  __half2 hp = __halves2half2(h0, h1);
  __half2 lp = __floats2half2_rn(r0, r1);
  uint2 u;
  u.x = *(uint32_t*)&hp;
  u.y = *(uint32_t*)&lp;
  return u;
}
__device__ __forceinline__ void mma16(float* d, uint32_t a0, uint32_t a1, uint32_t a2,
                                      uint32_t a3, uint32_t b0, uint32_t b1) {
  asm volatile(
      "mma.sync.aligned.m16n8k16.row.col.f32.f16.f16.f32 "
      "{%0,%1,%2,%3}, {%4,%5,%6,%7}, {%8,%9}, {%0,%1,%2,%3};"
      : "+f"(d[0]), "+f"(d[1]), "+f"(d[2]), "+f"(d[3])
      : "r"(a0), "r"(a1), "r"(a2), "r"(a3), "r"(b0), "r"(b1));
}
__device__ __forceinline__ void cpa16(void* smem_dst, const void* gsrc) {
  uint32_t s = (uint32_t)__cvta_generic_to_shared(smem_dst);
  asm volatile("cp.async.cg.shared.global [%0], [%1], 16;" :: "r"(s), "l"(gsrc));
}
#define CP_COMMIT asm volatile("cp.async.commit_group;")
#define CP_WAIT0  asm volatile("cp.async.wait_group 0;" ::: "memory")

#define RB 160    // B-tile row stride (payload 128B), conflict-free
#define ARB 1056  // full-A row stride (payload 1024B); 1056/4 = 264 ≡ 8 mod 32, same shift

// ---------------- compaction ----------------
__global__ __launch_bounds__(1024) void k_clear() {
  int i = blockIdx.x * 1024 + threadIdx.x;
  if (i < VOCAB) {
    g_flag[i] = 0;
    g_comp[i] = 0;
  }
  if (i == 0) g_count = 0;
}
__global__ __launch_bounds__(1024) void k_mark(const int* __restrict__ seq) {
  int i = blockIdx.x * 1024 + threadIdx.x;
  if (i >= NBATCH * (TCAND + 1)) return;
  int b = i / (TCAND + 1);
  int j = i - b * (TCAND + 1);
  int pos = (j < TCAND) ? j : (SEQT - 2);
  int tok = seq[b * SEQT + pos];
  if (atomicExch(&g_flag[tok], 1) == 0) {
    int id = atomicAdd(&g_count, 1);
    g_comp[tok] = id;
    g_list[id] = tok;
  }
}

// ---------------- prep: pre-split W1, W2 into pair format ----------------
__global__ __launch_bounds__(256) void k_prep(const float* __restrict__ W1,
                                              const float* __restrict__ W2) {
  int g = blockIdx.x * 256 + threadIdx.x;
  if (g < FDIM * 128) {
    int n = g >> 7, c = g & 127;
    g_w1p[n * 128 + c] = splitpair(W1[(2 * c) * FDIM + n], W1[(2 * c + 1) * FDIM + n]);
  } else {
    g -= FDIM * 128;
    if (g < HDIM * 256) {
      int n = g >> 8, c = g & 255;
      g_w2p[n * 256 + c] = splitpair(W2[(2 * c) * HDIM + n], W2[(2 * c + 1) * HDIM + n]);
    }
  }
}

// ============================================================================
// FFN1: t1 = relu(E[list] @ W1 + b1). Block = 128 rows x FULL N=512.
// A (128 x K=256, pre-split) resident in smem, staged ONCE. 4 N-groups of 128,
// each with 8 K-chunks of 32, B streamed via cp.async (L2-resident W1 pairs).
// ============================================================================
#define F1_A  0
#define F1_B0 135168
#define F1_B1 155648
#define F1_SMEM 176128

__global__ __launch_bounds__(512) void k_ffn1(const float* __restrict__ E,
                                              const float* __restrict__ b1) {
  extern __shared__ __align__(16) char sm[];
  __shared__ int slist[128];
  const int tid = threadIdx.x, lane = tid & 31, wid = tid >> 5;
  const int gr = lane >> 2, tc = lane & 3;
  const int wm = wid & 3, wn = wid >> 2;
  const int row0 = blockIdx.x * 128;

  const int cnt = g_count;
  if (row0 >= cnt) return;
  if (tid < 128) slist[tid] = (row0 + tid < cnt) ? g_list[row0 + tid] : -1;
  __syncthreads();

  // stage full A (split once per element)
#pragma unroll 4
  for (int l = 0; l < 16; l++) {
    int f = tid + l * 512;
    int r = f >> 6, fq = f & 63;
    int tok = slist[r];
    float4 v = make_float4(0.f, 0.f, 0.f, 0.f);
    if (tok >= 0) v = *(const float4*)(E + (size_t)tok * HDIM + fq * 4);
    uint2 u01 = splitpair(v.x, v.y), u23 = splitpair(v.z, v.w);
    *(uint4*)(sm + F1_A + r * ARB + fq * 16) = make_uint4(u01.x, u01.y, u23.x, u23.y);
  }
  // prologue: B tile (group 0, chunk 0)
#pragma unroll
  for (int l = 0; l < 2; l++) {
    int idx = tid + l * 512;
    int nr = idx >> 3, u = idx & 7;
    cpa16(sm + F1_B0 + nr * RB + u * 16, g_w1p + (size_t)nr * 128 + u * 2);
  }
  CP_COMMIT;
  __syncthreads();

  float acc0[2][4][4], acc1[2][4][4];
#pragma unroll
  for (int mt = 0; mt < 2; mt++)
#pragma unroll
    for (int nt = 0; nt < 4; nt++)
#pragma unroll
      for (int r = 0; r < 4; r++) { acc0[mt][nt][r] = 0.f; acc1[mt][nt][r] = 0.f; }

#pragma unroll 1
  for (int g = 0; g < 4; g++) {
#pragma unroll 1
    for (int ch = 0; ch < 8; ch++) {
      const int it = g * 8 + ch;
      char* Bb = sm + ((it & 1) ? F1_B1 : F1_B0);
      char* Bn = sm + ((it & 1) ? F1_B0 : F1_B1);
      CP_WAIT0;
      __syncthreads();
      if (it + 1 < 32) {
        int gn = (it + 1) >> 3, cn = (it + 1) & 7;
#pragma unroll
        for (int l = 0; l < 2; l++) {
          int idx = tid + l * 512;
          int nr = idx >> 3, u = idx & 7;
          cpa16(Bn + nr * RB + u * 16,
                g_w1p + (size_t)(gn * 128 + nr) * 128 + cn * 16 + u * 2);
        }
        CP_COMMIT;
      }
#pragma unroll
      for (int h = 0; h < 2; h++) {
        uint2 bf0[4], bf1[4];
#pragma unroll
        for (int nt = 0; nt < 4; nt++) {
          char* bp = Bb + (wn * 32 + nt * 8 + gr) * RB + (h * 8 + tc) * 8;
          bf0[nt] = *(uint2*)bp;
          bf1[nt] = *(uint2*)(bp + 32);
        }
#pragma unroll
        for (int mt = 0; mt < 2; mt++) {
          char* ap = sm + F1_A + (wm * 32 + mt * 16 + gr) * ARB + (ch * 16 + h * 8 + tc) * 8;
          uint2 a0 = *(uint2*)ap;
          uint2 a1 = *(uint2*)(ap + 8 * ARB);
          uint2 a2 = *(uint2*)(ap + 32);
          uint2 a3 = *(uint2*)(ap + 8 * ARB + 32);
#pragma unroll
          for (int nt = 0; nt < 4; nt++) {
            mma16(acc0[mt][nt], a0.x, a1.x, a2.x, a3.x, bf0[nt].x, bf1[nt].x);
            mma16(acc1[mt][nt], a0.x, a1.x, a2.x, a3.x, bf0[nt].y, bf1[nt].y);
            mma16(acc1[mt][nt], a0.y, a1.y, a2.y, a3.y, bf0[nt].x, bf1[nt].x);
          }
        }
      }
    }
    // epilogue for this N-group: combine, bias+relu, pre-split store; zero accs
    const int col0 = g * 128;
#pragma unroll
    for (int mt = 0; mt < 2; mt++) {
#pragma unroll
      for (int nt = 0; nt < 4; nt++) {
        int c0 = col0 + wn * 32 + nt * 8 + tc * 2;
        float bb0 = b1[c0], bb1 = b1[c0 + 1];
#pragma unroll
        for (int i = 0; i < 2; i++) {
          int row = row0 + wm * 32 + mt * 16 + gr + i * 8;
          if (row < cnt) {
            float v0 = fmaxf(acc0[mt][nt][i * 2] + acc1[mt][nt][i * 2] * INV2048 + bb0, 0.f);
            float v1 =
                fmaxf(acc0[mt][nt][i * 2 + 1] + acc1[mt][nt][i * 2 + 1] * INV2048 + bb1, 0.f);
            g_t1p[(size_t)row * 256 + (c0 >> 1)] = splitpair(v0, v1);
          }
          acc0[mt][nt][i * 2] = 0.f; acc0[mt][nt][i * 2 + 1] = 0.f;
          acc1[mt][nt][i * 2] = 0.f; acc1[mt][nt][i * 2 + 1] = 0.f;
        }
      }
    }
  }
}

// ============================================================================
// FFN2 over compact rows. Block 64x256 (full row), 512 thr. (unchanged)
// ============================================================================
#define F2_A0 0
#define F2_A1 10240
#define F2_B0 20480
#define F2_B1 61440
#define F2_PAR 102400
#define F2_PS  (F2_PAR + 4096)
#define F2_PS2 (F2_PS + 2048)
#define F2_PPG (F2_PS2 + 2048)
#define F2_MU  (F2_PPG + 2048)
#define F2_RS  (F2_MU + 256)
#define F2_SS  (F2_RS + 256)
#define F2_SMEM (F2_SS + 16)

__global__ __launch_bounds__(512) void k_ffn2(const float* __restrict__ E,
                                              const float* __restrict__ b2,
                                              const float* __restrict__ ln_g,
                                              const float* __restrict__ ln_b,
                                              const float* __restrict__ gate_w,
                                              const float* __restrict__ gate_b) {
  extern __shared__ __align__(16) char sm[];
  __shared__ int slist[64];
  float* sb2 = (float*)(sm + F2_PAR);
  float* slg = sb2 + 256;
  float* slb = slg + 256;
  float* sgg = slb + 256;
  float* pS = (float*)(sm + F2_PS);
  float* pS2 = (float*)(sm + F2_PS2);
  float* pPG = (float*)(sm + F2_PPG);
  float* sMU = (float*)(sm + F2_MU);
  float* sRS = (float*)(sm + F2_RS);
  float* sS = (float*)(sm + F2_SS);
  const int tid = threadIdx.x, lane = tid & 31, wid = tid >> 5;
  const int gr = lane >> 2, tc = lane & 3;
  const int wm = wid & 1, wn = wid >> 1;
  const int row0 = blockIdx.x * 64;

  const int cnt = g_count;
  if (row0 >= cnt) return;
  if (tid < 64) slist[tid] = (row0 + tid < cnt) ? g_list[row0 + tid] : -1;

  if (tid < 256) {
    float lg = ln_g[tid], lb = ln_b[tid], gw = gate_w[tid];
    sb2[tid] = b2[tid];
    slg[tid] = lg;
    slb[tid] = lb;
    sgg[tid] = lg * gw;
  }

  float acc0[2][4][4], acc1[2][4][4];
#pragma unroll
  for (int mt = 0; mt < 2; mt++)
#pragma unroll
    for (int nt = 0; nt < 4; nt++)
#pragma unroll
      for (int r = 0; r < 4; r++) { acc0[mt][nt][r] = 0.f; acc1[mt][nt][r] = 0.f; }

  {
    int nr = tid >> 3, u = tid & 7;
    cpa16(sm + F2_A0 + nr * RB + u * 16, g_t1p + (size_t)(row0 + nr) * 256 + u * 2);
#pragma unroll
    for (int l = 0; l < 4; l++) {
      int idx = tid + l * 512;
      int br = idx >> 3, bu = idx & 7;
      cpa16(sm + F2_B0 + br * RB + bu * 16, g_w2p + (size_t)br * 256 + bu * 2);
    }
    CP_COMMIT;
  }

#pragma unroll 1
  for (int ch = 0; ch < 16; ch++) {
    char* Ab = sm + ((ch & 1) ? F2_A1 : F2_A0);
    char* Bb = sm + ((ch & 1) ? F2_B1 : F2_B0);
    char* An = sm + ((ch & 1) ? F2_A0 : F2_A1);
    char* Bn = sm + ((ch & 1) ? F2_B0 : F2_B1);
    CP_WAIT0;
    __syncthreads();
    if (ch + 1 < 16) {
      int nr = tid >> 3, u = tid & 7;
      cpa16(An + nr * RB + u * 16,
            g_t1p + (size_t)(row0 + nr) * 256 + (ch + 1) * 16 + u * 2);
#pragma unroll
      for (int l = 0; l < 4; l++) {
        int idx = tid + l * 512;
        int br = idx >> 3, bu = idx & 7;
        cpa16(Bn + br * RB + bu * 16, g_w2p + (size_t)br * 256 + (ch + 1) * 16 + bu * 2);
      }
      CP_COMMIT;
    }
#pragma unroll
    for (int h = 0; h < 2; h++) {
      uint2 bf0[4], bf1[4];
#pragma unroll
      for (int nt = 0; nt < 4; nt++) {
        char* bp = Bb + (wn * 32 + nt * 8 + gr) * RB + (h * 8 + tc) * 8;
        bf0[nt] = *(uint2*)bp;
        bf1[nt] = *(uint2*)(bp + 32);
      }
#pragma unroll
      for (int mt = 0; mt < 2; mt++) {
        char* ap = Ab + (wm * 32 + mt * 16 + gr) * RB + (h * 8 + tc) * 8;
        uint2 a0 = *(uint2*)ap;
        uint2 a1 = *(uint2*)(ap + 8 * RB);
        uint2 a2 = *(uint2*)(ap + 32);
        uint2 a3 = *(uint2*)(ap + 8 * RB + 32);
#pragma unroll
        for (int nt = 0; nt < 4; nt++) {
          mma16(acc0[mt][nt], a0.x, a1.x, a2.x, a3.x, bf0[nt].x, bf1[nt].x);
          mma16(acc1[mt][nt], a0.x, a1.x, a2.x, a3.x, bf0[nt].y, bf1[nt].y);
          mma16(acc1[mt][nt], a0.y, a1.y, a2.y, a3.y, bf0[nt].x, bf1[nt].x);
        }
      }
    }
    __syncthreads();
  }

  if (wid == 0) {
    float a = 0.f, b = 0.f;
#pragma unroll
    for (int i = 0; i < 8; i++) {
      a += sgg[lane + 32 * i];
      b += slb[lane + 32 * i] * gate_w[lane + 32 * i];
    }
    a = wred_sum(a);
    b = wred_sum(b);
    if (lane == 0) { sS[0] = a; sS[1] = b + gate_b[0]; }
  }

#pragma unroll
  for (int mt = 0; mt < 2; mt++) {
#pragma unroll
    for (int i = 0; i < 2; i++) {
      int rl = wm * 32 + mt * 16 + gr + i * 8;
      int tok = slist[rl];
      bool valid = tok >= 0;
      float s = 0.f, sq = 0.f, pg = 0.f;
#pragma unroll
      for (int nt = 0; nt < 4; nt++) {
        int c0 = wn * 32 + nt * 8 + tc * 2;
        float2 ev = make_float2(0.f, 0.f);
        if (valid) ev = *(const float2*)(E + (size_t)tok * HDIM + c0);
        float x0 = acc0[mt][nt][i * 2] + acc1[mt][nt][i * 2] * INV2048 + sb2[c0] + ev.x;
        float x1 = acc0[mt][nt][i * 2 + 1] + acc1[mt][nt][i * 2 + 1] * INV2048 + sb2[c0 + 1] + ev.y;
        acc0[mt][nt][i * 2] = x0;
        acc0[mt][nt][i * 2 + 1] = x1;
        s += x0 + x1;
        sq += x0 * x0 + x1 * x1;
        pg += x0 * sgg[c0] + x1 * sgg[c0 + 1];
      }
      s += __shfl_xor_sync(0xffffffffu, s, 1);
      s += __shfl_xor_sync(0xffffffffu, s, 2);
      sq += __shfl_xor_sync(0xffffffffu, sq, 1);
      sq += __shfl_xor_sync(0xffffffffu, sq, 2);
      pg += __shfl_xor_sync(0xffffffffu, pg, 1);
      pg += __shfl_xor_sync(0xffffffffu, pg, 2);
      if (tc == 0) {
        pS[wn * 64 + rl] = s;
        pS2[wn * 64 + rl] = sq;
        pPG[wn * 64 + rl] = pg;
      }
    }
  }
  __syncthreads();
  if (tid < 64) {
    float s = 0.f, sq = 0.f, pg = 0.f;
#pragma unroll
    for (int w = 0; w < 8; w++) {
      s += pS[w * 64 + tid];
      sq += pS2[w * 64 + tid];
      pg += pPG[w * 64 + tid];
    }
    float mu = s * (1.f / 256.f);
    float var = sq * (1.f / 256.f) - mu * mu;
    float rs = rsqrtf(var + 1e-5f);
    sMU[tid] = mu;
    sRS[tid] = rs;
    int rg = row0 + tid;
    if (rg < cnt) g_score[rg] = rs * (pg - mu * sS[0]) + sS[1];
  }
  __syncthreads();

#pragma unroll
  for (int mt = 0; mt < 2; mt++) {
#pragma unroll
    for (int i = 0; i < 2; i++) {
      int rl = wm * 32 + mt * 16 + gr + i * 8;
      int rg = row0 + rl;
      if (rg >= cnt) continue;
      float mu = sMU[rl], rs = sRS[rl];
#pragma unroll
      for (int nt = 0; nt < 4; nt++) {
        int c0 = wn * 32 + nt * 8 + tc * 2;
        float2 o;
        o.x = (acc0[mt][nt][i * 2] - mu) * rs * slg[c0] + slb[c0];
        o.y = (acc0[mt][nt][i * 2 + 1] - mu) * rs * slg[c0 + 1] + slb[c0 + 1];
        *(float2*)(g_hidden + (size_t)rg * HDIM + c0) = o;
      }
    }
  }
}

// ============================================================================
// Pass 3: per-batch top-512 via radix-select (pivot by byte-level histograms).
// Selected SET identical to full sort (ties: smaller index first, = jax).
// Output slots assigned by deterministic block scans.
// ============================================================================
__global__ __launch_bounds__(1024) void k_topk(const int* __restrict__ seq) {
  __shared__ uint32_t ukey[4096];
  __shared__ int hist[256];
  __shared__ int wsum[32];
  __shared__ uint32_t sPiv;
  __shared__ int sNeed, sTA;
  const int b = blockIdx.x;
  const int tid = threadIdx.x;
  const int lane = tid & 31, w = tid >> 5;

  if (tid < 256) hist[tid] = 0;
  for (int i = tid; i < 4096; i += 1024) {
    if (i < TCAND) {
      float f = g_score[g_comp[seq[b * SEQT + i]]];
      uint32_t bits = __float_as_uint(f);
      ukey[i] = (bits & 0x80000000u) ? ~bits : (bits | 0x80000000u);
    } else {
      ukey[i] = 0u;  // smaller than any real key's transform (real keys have bit31 context)
    }
  }
  __syncthreads();

  // NOTE: padding keys (0u) could collide with a real key only if a real score's
  // transform is exactly 0 (i.e. score = -inf pattern) — impossible for finite scores
  // (negative f -> ~bits != 0 since bits has sign bit set). Padding is never selected
  // because guards below use i < TCAND anyway.

  uint32_t P = 0;
  int need = MSEL;
#pragma unroll 1
  for (int lvl = 3; lvl >= 0; lvl--) {
    uint32_t mh = (lvl == 3) ? 0u : (0xFFFFFFFFu << ((lvl + 1) * 8));
    for (int i = tid; i < TCAND; i += 1024) {
      uint32_t u = ukey[i];
      if ((u & mh) == P) atomicAdd(&hist[(u >> (lvl * 8)) & 255], 1);
    }
    __syncthreads();
    if (tid == 0) {
      int run = 0, bsel = 0;
      for (int bin = 255; bin >= 0; bin--) {
        int c = hist[bin];
        if (run + c >= need) { bsel = bin; break; }
        run += c;
      }
      sPiv = P | ((uint32_t)bsel << (lvl * 8));
      sNeed = need - run;
    }
    __syncthreads();
    P = sPiv;
    need = sNeed;
    if (tid < 256) hist[tid] = 0;
    __syncthreads();
  }

  // scan 1: elements with ukey > P (all selected); assign slots in index order
  const int base = tid * 4;
  int loc[4];
  int cnt = 0;
#pragma unroll
  for (int e = 0; e < 4; e++) {
    int i = base + e;
    int f = (i < TCAND && ukey[i] > P) ? 1 : 0;
    loc[e] = cnt;
    cnt += f;
  }
  int sc = cnt;
#pragma unroll
  for (int o = 1; o < 32; o <<= 1) {
    int v = __shfl_up_sync(0xffffffffu, sc, o);
    if (lane >= o) sc += v;
  }
  if (lane == 31) wsum[w] = sc;
  __syncthreads();
  if (w == 0) {
    int t = wsum[lane];
    int ts = t;
#pragma unroll
    for (int o = 1; o < 32; o <<= 1) {
      int v = __shfl_up_sync(0xffffffffu, ts, o);
      if (lane >= o) ts += v;
    }
    wsum[lane] = ts - t;
  }
  __syncthreads();
  int off = wsum[w] + (sc - cnt);
  if (tid == 1023) sTA = off + cnt;
#pragma unroll
  for (int e = 0; e < 4; e++) {
    int i = base + e;
    if (i < TCAND && ukey[i] > P)
      g_mem_tok[b * MSEL + off + loc[e]] = g_comp[seq[b * SEQT + i]];
  }
  __syncthreads();
  const int TA = sTA;  // = MSEL - need

  // scan 2: elements with ukey == P; select first `need` by index (jax tie-break)
  int cnt2 = 0;
#pragma unroll
  for (int e = 0; e < 4; e++) {
    int i = base + e;
    int f = (i < TCAND && ukey[i] == P) ? 1 : 0;
    loc[e] = cnt2;
    cnt2 += f;
  }
  int sc2 = cnt2;
#pragma unroll
  for (int o = 1; o < 32; o <<= 1) {
    int v = __shfl_up_sync(0xffffffffu, sc2, o);
    if (lane >= o) sc2 += v;
  }
  if (lane == 31) wsum[w] = sc2;
  __syncthreads();
  if (w == 0) {
    int t = wsum[lane];
    int ts = t;
#pragma unroll
    for (int o = 1; o < 32; o <<= 1) {
      int v = __shfl_up_sync(0xffffffffu, ts, o);
      if (lane >= o) ts += v;
    }
    wsum[lane] = ts - t;
  }
  __syncthreads();
  int off2 = wsum[w] + (sc2 - cnt2);
#pragma unroll
  for (int e = 0; e < 4; e++) {
    int i = base + e;
    if (i < TCAND && ukey[i] == P) {
      int r = off2 + loc[e];
      if (r < need) g_mem_tok[b * MSEL + TA + r] = g_comp[seq[b * SEQT + i]];
    }
  }
}

// ---------------- Pass 4: query proj + attention + context ----------------
__global__ __launch_bounds__(1024) void k_attn(const int* __restrict__ seq,
                                               const float* __restrict__ qa_w,
                                               const float* __restrict__ qa_b,
                                               const float* __restrict__ qr_w,
                                               const float* __restrict__ qr_b) {
  __shared__ float hq[HDIM], q1[HDIM], q2[HDIM];
  __shared__ float att[MSEL];
  __shared__ int stok[MSEL];
  __shared__ float part[4][HDIM];
  __shared__ float red[32];
  __shared__ float sred[2];
  const int b = blockIdx.x;
  const int tid = threadIdx.x;
  const int lane = tid & 31, w = tid >> 5;
  const int o = tid & 255, p = tid >> 8;

  if (tid < 256) {
    int cq = g_comp[seq[b * SEQT + (SEQT - 2)]];
    hq[tid] = g_hidden[(size_t)cq * HDIM + tid];
  }
  if (tid < MSEL) stok[tid] = g_mem_tok[b * MSEL + tid];
  __syncthreads();

  {
    float s = 0.f;
#pragma unroll 8
    for (int h = p * 64; h < p * 64 + 64; h++) s = fmaf(hq[h], qa_w[h * HDIM + o], s);
    part[p][o] = s;
  }
  __syncthreads();
  if (tid < 256) q1[tid] = qa_b[tid] + part[0][tid] + part[1][tid] + part[2][tid] + part[3][tid];
  __syncthreads();
  {
    float s = 0.f;
#pragma unroll 8
    for (int h = p * 64; h < p * 64 + 64; h++) s = fmaf(q1[h], qr_w[h * HDIM + o], s);
    part[p][o] = s;
  }
  __syncthreads();
  if (tid < 256) q2[tid] = qr_b[tid] + part[0][tid] + part[1][tid] + part[2][tid] + part[3][tid];
  __syncthreads();

#pragma unroll 2
  for (int t = 0; t < 16; t++) {
    int m = w * 16 + t;
    const float* row = g_hidden + (size_t)stok[m] * HDIM;
    float s = 0.f;
#pragma unroll
    for (int c = 0; c < 8; c++) s = fmaf(row[lane + 32 * c], q2[lane + 32 * c], s);
    s = wred_sum(s);
    if (lane == 0) att[m] = s;
  }
  __syncthreads();

  float v = (tid < MSEL) ? att[tid] : -INFINITY;
  float mx = v;
#pragma unroll
  for (int off = 16; off > 0; off >>= 1) mx = fmaxf(mx, __shfl_xor_sync(0xffffffffu, mx, off));
  if (lane == 0) red[w] = mx;
  __syncthreads();
  if (w == 0) {
    float m2 = red[lane];
#pragma unroll
    for (int off = 16; off > 0; off >>= 1) m2 = fmaxf(m2, __shfl_xor_sync(0xffffffffu, m2, off));
    if (lane == 0) sred[0] = m2;
  }
  __syncthreads();
  float gmx = sred[0];
  float e = (tid < MSEL) ? expf(v - gmx) : 0.f;
  if (tid < MSEL) att[tid] = e;
  float ssum = wred_sum(e);
  __syncthreads();
  if (lane == 0) red[w] = ssum;
  __syncthreads();
  if (w == 0) {
    float s2 = red[lane];
    s2 = wred_sum(s2);
    if (lane == 0) sred[1] = s2;
  }
  __syncthreads();
  float inv = 1.f / sred[1];

  {
    float c = 0.f;
#pragma unroll 4
    for (int m = p * 128; m < p * 128 + 128; m++)
      c = fmaf(att[m], g_hidden[(size_t)stok[m] * HDIM + o], c);
    part[p][o] = c;
  }
  __syncthreads();
  if (tid < 256)
    g_ctx[b * HDIM + tid] = (part[0][tid] + part[1][tid] + part[2][tid] + part[3][tid]) * inv;
}

// ---------------- Pass 5: out = ctx @ out_w + out_b ----------------
__global__ __launch_bounds__(256) void k_out(const float* __restrict__ Wo,
                                             const float* __restrict__ bo,
                                             float* __restrict__ out) {
  __shared__ float cs[NBATCH * HDIM];
  const int tid = threadIdx.x;
  for (int i = tid; i < NBATCH * HDIM; i += 256) cs[i] = g_ctx[i];
  __syncthreads();
  int v = blockIdx.x * 256 + tid;
  if (v >= VOCAB) return;
  float accv[NBATCH];
  float bias = bo[v];
#pragma unroll
  for (int b = 0; b < NBATCH; b++) accv[b] = bias;
#pragma unroll 8
  for (int h = 0; h < HDIM; h++) {
    float wv = Wo[(size_t)h * VOCAB + v];
#pragma unroll
    for (int b = 0; b < NBATCH; b++) accv[b] = fmaf(cs[b * HDIM + h], wv, accv[b]);
  }
#pragma unroll
  for (int b = 0; b < NBATCH; b++) out[(size_t)b * VOCAB + v] = accv[b];
}

// ---------------- launch ----------------
extern "C" void kernel_launch(void* const* d_in, const int* in_sizes, int n_in,
                              void* d_out, int out_size) {
  const int* seq = (const int*)d_in[0];
  const float* embed = (const float*)d_in[1];
  const float* W1 = (const float*)d_in[2];
  const float* b1 = (const float*)d_in[3];
  const float* W2 = (const float*)d_in[4];
  const float* b2 = (const float*)d_in[5];
  const float* ln_g = (const float*)d_in[6];
  const float* ln_b = (const float*)d_in[7];
  const float* gate_w = (const float*)d_in[8];
  const float* gate_b = (const float*)d_in[9];
  const float* qa_w = (const float*)d_in[10];
  const float* qa_b = (const float*)d_in[11];
  const float* qr_w = (const float*)d_in[12];
  const float* qr_b = (const float*)d_in[13];
  const float* out_w = (const float*)d_in[14];
  const float* out_b = (const float*)d_in[15];
  float* out = (float*)d_out;

  cudaFuncSetAttribute(k_ffn1, cudaFuncAttributeMaxDynamicSharedMemorySize, F1_SMEM);
  cudaFuncSetAttribute(k_ffn2, cudaFuncAttributeMaxDynamicSharedMemorySize, F2_SMEM);

  k_clear<<<(VOCAB + 1023) / 1024, 1024>>>();
  k_mark<<<(NBATCH * (TCAND + 1) + 1023) / 1024, 1024>>>(seq);
  k_prep<<<512, 256>>>(W1, W2);
  k_ffn1<<<(VOCAB + 127) / 128, 512, F1_SMEM>>>(embed, b1);
  k_ffn2<<<(VOCAB + 63) / 64, 512, F2_SMEM>>>(embed, b2, ln_g, ln_b, gate_w, gate_b);
  k_topk<<<NBATCH, 1024>>>(seq);
  k_attn<<<NBATCH, 1024>>>(seq, qa_w, qa_b, qr_w, qr_b);
  k_out<<<(VOCAB + 255) / 256, 256>>>(out_w, out_b, out);
}